// round 7
// baseline (speedup 1.0000x reference)
#include <cuda_runtime.h>
#include <math.h>
#include <stdint.h>

// ---------------- problem constants ----------------
#define BATCH   2
#define SEQ     8192
#define DMODEL  512
#define NH      8
#define DH      64
#define BHEADS  16
#define BNROWS  16384
#define QKVN    1536
#define HID     1365
#define HID2    2730
#define HID2P   2816   // FF1 N (interleaved a/gate pairs) padded to mult of 256
#define KFF2    1408   // FF2 K padded to mult of 32 (= HID2P/2)
#define WSIZE   512

// ---------------- scratch buffers ----------------
__device__ float g_h    [(size_t)BNROWS * DMODEL];
__device__ float g_qkv  [(size_t)BNROWS * QKVN];
__device__ float g_q    [(size_t)BHEADS * SEQ * DH];
__device__ float g_k    [(size_t)BHEADS * SEQ * DH];
__device__ float g_v    [(size_t)BHEADS * SEQ * DH];
__device__ float g_o    [(size_t)BNROWS * DMODEL];
__device__ float g_x1   [(size_t)BNROWS * DMODEL];
__device__ float g_gate [(size_t)BNROWS * KFF2];
__device__ float g_Wqkvc[(size_t)DMODEL * QKVN];
__device__ float g_Woutc[(size_t)DMODEL * DMODEL];
__device__ float g_W1i  [(size_t)DMODEL * HID2P];   // interleaved a/gate cols
__device__ float g_W2p  [(size_t)KFF2 * DMODEL];    // rows >= HID are zero
__device__ float g_b1i  [HID2P];

// ---------------- helpers ----------------
__device__ __forceinline__ unsigned f2tf32(float f) {
    unsigned u;
    asm("cvt.rna.tf32.f32 %0, %1;" : "=r"(u) : "f"(f));
    return u;
}
__device__ __forceinline__ float tf32r(float f) { return __uint_as_float(f2tf32(f)); }
__device__ __forceinline__ float ex2f(float x) {
    float y;
    asm("ex2.approx.f32 %0, %1;" : "=f"(y) : "f"(x));
    return y;
}
__device__ __forceinline__ void mma_tf32(float c[4], const unsigned a[4], const unsigned b[2]) {
    asm volatile(
        "mma.sync.aligned.m16n8k8.row.col.f32.tf32.tf32.f32 "
        "{%0,%1,%2,%3}, {%4,%5,%6,%7}, {%8,%9}, {%0,%1,%2,%3};"
        : "+f"(c[0]), "+f"(c[1]), "+f"(c[2]), "+f"(c[3])
        : "r"(a[0]), "r"(a[1]), "r"(a[2]), "r"(a[3]), "r"(b[0]), "r"(b[1]));
}
__device__ __forceinline__ void cp16(float* s, const float* g) {
    unsigned sa = (unsigned)__cvta_generic_to_shared(s);
    asm volatile("cp.async.cg.shared.global [%0], [%1], 16;" :: "r"(sa), "l"(g));
}
__device__ __forceinline__ void cp_commit() { asm volatile("cp.async.commit_group;"); }
template<int NN> __device__ __forceinline__ void cp_wait() {
    asm volatile("cp.async.wait_group %0;" :: "n"(NN));
}

// ---------------- weight prep kernels ----------------
__global__ void cvt_kernel(const float* __restrict__ src, float* __restrict__ dst, int n)
{
    int i = blockIdx.x * 256 + threadIdx.x;
    if (i < n) dst[i] = tf32r(src[i]);
}
__global__ void cvt_w1i_kernel(const float* __restrict__ W1)
{
    long i = (long)blockIdx.x * 256 + threadIdx.x;
    if (i >= (long)DMODEL * HID2P) return;
    int k = (int)(i / HID2P), j = (int)(i - (long)k * HID2P);
    float v = 0.0f;
    if (j < HID2) {
        int c = (j >> 1) + (j & 1) * HID;
        v = tf32r(W1[(size_t)k * HID2 + c]);
    }
    g_W1i[(size_t)k * HID2P + j] = v;
}
__global__ void cvt_w2p_kernel(const float* __restrict__ W2)
{
    long i = (long)blockIdx.x * 256 + threadIdx.x;
    if (i >= (long)KFF2 * DMODEL) return;
    int r = (int)(i / DMODEL);
    g_W2p[i] = (r < HID) ? tf32r(W2[i]) : 0.0f;
}
__global__ void b1i_kernel(const float* __restrict__ b1)
{
    int j = blockIdx.x * 256 + threadIdx.x;
    if (j < HID2P) g_b1i[j] = (j < HID2) ? b1[(j >> 1) + (j & 1) * HID] : 0.0f;
}

// ---------------- LayerNorm (emits tf32-rounded values) ----------------
__global__ void ln_kernel(const float* __restrict__ x,
                          const float* __restrict__ gamma,
                          const float* __restrict__ beta,
                          float* __restrict__ out)
{
    int row = blockIdx.x;
    int tid = threadIdx.x;
    const float* xr = x + (size_t)row * DMODEL;
    float v0 = xr[tid];
    float v1 = xr[tid + 256];
    float s  = v0 + v1;
    float ss = v0 * v0 + v1 * v1;

    __shared__ float shs[8], shss[8];
    #pragma unroll
    for (int o = 16; o > 0; o >>= 1) {
        s  += __shfl_down_sync(0xffffffffu, s,  o);
        ss += __shfl_down_sync(0xffffffffu, ss, o);
    }
    if ((tid & 31) == 0) { shs[tid >> 5] = s; shss[tid >> 5] = ss; }
    __syncthreads();
    if (tid < 8) {
        s = shs[tid]; ss = shss[tid];
        #pragma unroll
        for (int o = 4; o > 0; o >>= 1) {
            s  += __shfl_down_sync(0xffu, s,  o);
            ss += __shfl_down_sync(0xffu, ss, o);
        }
        if (tid == 0) { shs[0] = s; shss[0] = ss; }
    }
    __syncthreads();
    float mean = shs[0]  * (1.0f / DMODEL);
    float var  = shss[0] * (1.0f / DMODEL) - mean * mean;
    float inv  = rsqrtf(var + 1e-5f);
    float* outr = out + (size_t)row * DMODEL;
    outr[tid]       = tf32r((v0 - mean) * inv * gamma[tid]       + beta[tid]);
    outr[tid + 256] = tf32r((v1 - mean) * inv * gamma[tid + 256] + beta[tid + 256]);
}

// ---------------- mma.sync tf32 GEMM, 128x256 CTA tile ----------------
// C(MxN) = A(MxK, lda) @ B(KxN, ldb) ; 256 threads, 8 warps (2m x 4n),
// warp tile 64x64, BK=32, 2-stage cp.async. Requirements: M%128==0,
// N%256==0, K%32==0, lda/ldb mult of 4. Inputs pre-rounded to tf32.
// MODE: 0 plain, 1 +res, 2 +bias & geglu-pair -> half-width store, 3 +bias+res
#define SM_A_OFF 0
#define SM_B_OFF (2 * 128 * 36)
#define GEMM_SMEM ((2 * 128 * 36 + 2 * 32 * 260) * 4)

__device__ __forceinline__ void gemm_stage(
    float (*As)[36], float (*Bs)[260],
    const float* __restrict__ A, const float* __restrict__ B,
    int m0, int n0, int k0, int lda, int ldb, int tid)
{
    #pragma unroll
    for (int i = 0; i < 4; i++) {
        int idx = i * 256 + tid;
        int row = idx >> 3, c4 = (idx & 7) * 4;
        cp16(&As[row][c4], A + (size_t)(m0 + row) * lda + k0 + c4);
    }
    #pragma unroll
    for (int i = 0; i < 8; i++) {
        int idx = i * 256 + tid;
        int row = idx >> 6, c4 = (idx & 63) * 4;
        cp16(&Bs[row][c4], B + (size_t)(k0 + row) * ldb + n0 + c4);
    }
    cp_commit();
}

template<int MODE>
__global__ void __launch_bounds__(256)
gemm_mma(const float* __restrict__ A, const float* __restrict__ B,
         const float* __restrict__ bias, const float* __restrict__ res,
         float* __restrict__ C, int N, int K, int lda, int ldb, int ldc)
{
    extern __shared__ float smf[];
    float (*As)[36]  = (float (*)[36])(smf + SM_A_OFF);
    float (*Bs)[260] = (float (*)[260])(smf + SM_B_OFF);

    int tid  = threadIdx.x;
    int lane = tid & 31;
    int wid  = tid >> 5;
    int g  = lane >> 2;
    int tg = lane & 3;
    int wm = (wid & 1) * 64;
    int wn = (wid >> 1) * 64;
    int m0 = blockIdx.y * 128, n0 = blockIdx.x * 256;

    float c[4][8][4];
    #pragma unroll
    for (int i = 0; i < 4; i++)
        #pragma unroll
        for (int j = 0; j < 8; j++)
            #pragma unroll
            for (int l = 0; l < 4; l++) c[i][j][l] = 0.0f;

    int T = K >> 5;
    gemm_stage(As, Bs, A, B, m0, n0, 0, lda, ldb, tid);

    for (int kt = 0; kt < T; kt++) {
        int buf = kt & 1;
        if (kt + 1 < T) {
            gemm_stage(As + (buf ^ 1) * 128, Bs + (buf ^ 1) * 32,
                       A, B, m0, n0, (kt + 1) * 32, lda, ldb, tid);
            cp_wait<1>();
        } else {
            cp_wait<0>();
        }
        __syncthreads();

        float (*Ab)[36]  = As + buf * 128;
        float (*Bb)[260] = Bs + buf * 32;
        #pragma unroll
        for (int ks = 0; ks < 4; ks++) {
            unsigned a[4][4], b[8][2];
            #pragma unroll
            for (int mf = 0; mf < 4; mf++) {
                int row = wm + mf * 16 + g;
                int col = ks * 8 + tg;
                a[mf][0] = __float_as_uint(Ab[row][col]);
                a[mf][1] = __float_as_uint(Ab[row + 8][col]);
                a[mf][2] = __float_as_uint(Ab[row][col + 4]);
                a[mf][3] = __float_as_uint(Ab[row + 8][col + 4]);
            }
            #pragma unroll
            for (int nf = 0; nf < 8; nf++) {
                int col = wn + nf * 8 + g;
                b[nf][0] = __float_as_uint(Bb[ks * 8 + tg][col]);
                b[nf][1] = __float_as_uint(Bb[ks * 8 + tg + 4][col]);
            }
            #pragma unroll
            for (int mf = 0; mf < 4; mf++)
                #pragma unroll
                for (int nf = 0; nf < 8; nf++)
                    mma_tf32(c[mf][nf], a[mf], b[nf]);
        }
        __syncthreads();
    }

    #pragma unroll
    for (int mf = 0; mf < 4; mf++) {
        int r0 = m0 + wm + mf * 16 + g;
        #pragma unroll
        for (int nf = 0; nf < 8; nf++) {
            int col = n0 + wn + nf * 8 + 2 * tg;
            #pragma unroll
            for (int half = 0; half < 2; half++) {
                int r = r0 + half * 8;
                float cx = c[mf][nf][half * 2];
                float cy = c[mf][nf][half * 2 + 1];
                if (MODE == 0) {
                    *(float2*)&C[(size_t)r * ldc + col] = make_float2(cx, cy);
                } else if (MODE == 1) {
                    float2 rr = *(const float2*)&res[(size_t)r * ldc + col];
                    *(float2*)&C[(size_t)r * ldc + col] =
                        make_float2(cx + rr.x, cy + rr.y);
                } else if (MODE == 2) {
                    float xa = cx + bias[col];
                    float yg = cy + bias[col + 1];
                    float ge = 0.5f * yg * (1.0f + erff(yg * 0.70710678118654752f));
                    C[(size_t)r * ldc + (col >> 1)] = tf32r(xa * ge);
                } else {
                    float2 rr = *(const float2*)&res[(size_t)r * ldc + col];
                    *(float2*)&C[(size_t)r * ldc + col] =
                        make_float2(cx + bias[col] + rr.x,
                                    cy + bias[col + 1] + rr.y);
                }
            }
        }
    }
}

// ---------------- QKV split + l2norm + scale + rotary xpos ----------------
__global__ void qkv_rotary_kernel(const float* __restrict__ q_scale,
                                  const float* __restrict__ k_scale)
{
    int lane = threadIdx.x & 31;
    int warp = threadIdx.x >> 5;
    long task = (long)blockIdx.x * 4 + warp;
    int b = (int)(task / ((long)SEQ * NH));
    long rem = task - (long)b * SEQ * NH;
    int n = (int)(rem / NH);
    int h = (int)(rem - (long)n * NH);

    size_t base = ((size_t)b * SEQ + n) * QKVN + (size_t)h * DH;
    float q0 = g_qkv[base + lane],        q1 = g_qkv[base + 32 + lane];
    float k0 = g_qkv[base + 512 + lane],  k1 = g_qkv[base + 512 + 32 + lane];
    float v0 = g_qkv[base + 1024 + lane], v1 = g_qkv[base + 1024 + 32 + lane];

    float sq = q0 * q0 + q1 * q1;
    float sk = k0 * k0 + k1 * k1;
    #pragma unroll
    for (int o = 16; o > 0; o >>= 1) {
        sq += __shfl_xor_sync(0xffffffffu, sq, o);
        sk += __shfl_xor_sync(0xffffffffu, sk, o);
    }
    float qinv = 1.0f / fmaxf(sqrtf(sq), 1e-12f);
    float kinv = 1.0f / fmaxf(sqrtf(sk), 1e-12f);
    q0 = q0 * qinv * q_scale[lane];
    q1 = q1 * qinv * q_scale[lane + 32];
    k0 = k0 * kinv * k_scale[lane];
    k1 = k1 * kinv * k_scale[lane + 32];

    float t    = (float)n;
    float invf = exp2f((float)lane * (-13.287712379549449f / 32.0f));
    float fr   = t * invf;
    float cs = cosf(fr), sn = sinf(fr);
    float sv = (2.0f * (float)lane + 0.4f * 64.0f) / (1.4f * 64.0f);
    float pw = (t - (float)(SEQ / 2)) / (float)(WSIZE / 2);
    float xs = exp2f(pw * log2f(sv));
    float ixs = 1.0f / xs;

    const float QSC = 11.541560327111708f;   // 8 * log2(e)
    float qo0 = (q0 * cs - q1 * sn) * xs;
    float qo1 = (q1 * cs + q0 * sn) * xs;
    float ko0 = (k0 * cs - k1 * sn) * ixs;
    float ko1 = (k1 * cs + k0 * sn) * ixs;

    size_t obase = ((size_t)(b * NH + h) * SEQ + n) * DH;
    g_q[obase + lane]      = tf32r(QSC * qo0);
    g_q[obase + 32 + lane] = tf32r(QSC * qo1);
    g_k[obase + lane]      = tf32r(ko0);
    g_k[obase + 32 + lane] = tf32r(ko1);
    g_v[obase + lane]      = tf32r(v0);
    g_v[obase + 32 + lane] = tf32r(v1);
}

// ---------------- tensor-core local windowed attention ----------------
__device__ __forceinline__ void attn_stage(
    float (*Ks)[68], float (*Vs)[68],
    const float* kbase, const float* vbase, int kg0, int tid)
{
    #pragma unroll
    for (int i = 0; i < 4; i++) {
        int idx = i * 256 + tid;
        int kk = idx >> 4, d4 = idx & 15;
        size_t off = (size_t)(kg0 + kk) * DH + d4 * 4;
        cp16(&Ks[kk][d4 * 4], kbase + off);
        cp16(&Vs[kk][d4 * 4], vbase + off);
    }
    cp_commit();
}

__global__ void __launch_bounds__(256) attn_kernel()
{
    __shared__ float Ks[2][64][68];
    __shared__ float Vs[2][64][68];

    const int tid  = threadIdx.x;
    const int lane = tid & 31;
    const int wq   = tid >> 5;
    const int g    = lane >> 2;
    const int tg   = lane & 3;
    const int qb   = blockIdx.x;
    const int bh   = blockIdx.y;
    const int t0   = qb * 128;
    const int w    = t0 >> 9;
    const int rstart = (w > 0) ? 0 : ((512 - (t0 & 511)) >> 6);

    unsigned qf[8][4];
    {
        const float* qb0 = g_q + ((size_t)bh * SEQ + t0 + wq * 16) * DH;
        #pragma unroll
        for (int kc = 0; kc < 8; kc++) {
            qf[kc][0] = __float_as_uint(qb0[(size_t)g * DH + kc * 8 + tg]);
            qf[kc][1] = __float_as_uint(qb0[(size_t)(g + 8) * DH + kc * 8 + tg]);
            qf[kc][2] = __float_as_uint(qb0[(size_t)g * DH + kc * 8 + tg + 4]);
            qf[kc][3] = __float_as_uint(qb0[(size_t)(g + 8) * DH + kc * 8 + tg + 4]);
        }
    }

    float o[8][4];
    #pragma unroll
    for (int i = 0; i < 8; i++)
        #pragma unroll
        for (int j = 0; j < 4; j++) o[i][j] = 0.0f;
    float d0 = 0.0f, d1 = 0.0f;

    const float* kbase = g_k + (size_t)bh * SEQ * DH;
    const float* vbase = g_v + (size_t)bh * SEQ * DH;

    attn_stage(Ks[0], Vs[0], kbase, vbase, t0 - 512 + 64 * rstart, tid);

    const int q0r = wq * 16 + g;

    for (int r = rstart; r <= 9; r++) {
        int buf = (r - rstart) & 1;
        if (r < 9) {
            attn_stage(Ks[buf ^ 1], Vs[buf ^ 1], kbase, vbase,
                       t0 - 512 + 64 * (r + 1), tid);
            cp_wait<1>();
        } else {
            cp_wait<0>();
        }
        __syncthreads();

        float s[8][4];
        #pragma unroll
        for (int i = 0; i < 8; i++)
            #pragma unroll
            for (int j = 0; j < 4; j++) s[i][j] = 0.0f;

        #pragma unroll
        for (int kc = 0; kc < 8; kc++) {
            #pragma unroll
            for (int nf = 0; nf < 8; nf++) {
                unsigned b[2];
                b[0] = __float_as_uint(Ks[buf][nf * 8 + g][kc * 8 + tg]);
                b[1] = __float_as_uint(Ks[buf][nf * 8 + g][kc * 8 + tg + 4]);
                mma_tf32(s[nf], qf[kc], b);
            }
        }

        float p[8][4];
        #pragma unroll
        for (int nf = 0; nf < 8; nf++) {
            int j0  = nf * 8 + 2 * tg;
            int jr0 = 64 * r - 512 + j0;
            int jr1 = jr0 + 1;
            bool ok0 = (jr0 <= q0r)     && (jr0 >= q0r - 512);
            bool ok1 = (jr1 <= q0r)     && (jr1 >= q0r - 512);
            bool ok2 = (jr0 <= q0r + 8) && (jr0 >= q0r - 504);
            bool ok3 = (jr1 <= q0r + 8) && (jr1 >= q0r - 504);
            p[nf][0] = ok0 ? ex2f(s[nf][0]) : 0.0f;
            p[nf][1] = ok1 ? ex2f(s[nf][1]) : 0.0f;
            p[nf][2] = ok2 ? ex2f(s[nf][2]) : 0.0f;
            p[nf][3] = ok3 ? ex2f(s[nf][3]) : 0.0f;
            d0 += p[nf][0] + p[nf][1];
            d1 += p[nf][2] + p[nf][3];
        }

        #pragma unroll
        for (int kc = 0; kc < 8; kc++) {
            unsigned a[4];
            a[0] = f2tf32(p[kc][0]);
            a[1] = f2tf32(p[kc][2]);
            a[2] = f2tf32(p[kc][1]);
            a[3] = f2tf32(p[kc][3]);
            #pragma unroll
            for (int nf = 0; nf < 8; nf++) {
                unsigned b[2];
                b[0] = __float_as_uint(Vs[buf][kc * 8 + 2 * tg][nf * 8 + g]);
                b[1] = __float_as_uint(Vs[buf][kc * 8 + 2 * tg + 1][nf * 8 + g]);
                mma_tf32(o[nf], a, b);
            }
        }
        __syncthreads();
    }

    d0 += __shfl_xor_sync(0xffffffffu, d0, 1);
    d0 += __shfl_xor_sync(0xffffffffu, d0, 2);
    d1 += __shfl_xor_sync(0xffffffffu, d1, 1);
    d1 += __shfl_xor_sync(0xffffffffu, d1, 2);
    float i0 = 1.0f / d0, i1 = 1.0f / d1;

    int b = bh >> 3, h = bh & 7;
    int row0 = t0 + wq * 16 + g;
    float* ob = g_o + (size_t)b * SEQ * DMODEL + h * DH;
    #pragma unroll
    for (int nf = 0; nf < 8; nf++) {
        int col = nf * 8 + 2 * tg;
        float2 lo = make_float2(tf32r(o[nf][0] * i0), tf32r(o[nf][1] * i0));
        float2 hi = make_float2(tf32r(o[nf][2] * i1), tf32r(o[nf][3] * i1));
        *(float2*)&ob[(size_t)row0 * DMODEL + col]       = lo;
        *(float2*)&ob[(size_t)(row0 + 8) * DMODEL + col] = hi;
    }
}

// ---------------- launch ----------------
extern "C" void kernel_launch(void* const* d_in, const int* in_sizes, int n_in,
                              void* d_out, int out_size)
{
    const float* x     = (const float*)d_in[0];
    const float* ln1g  = (const float*)d_in[1];
    const float* ln1b  = (const float*)d_in[2];
    const float* Wqkv  = (const float*)d_in[3];
    const float* qsc   = (const float*)d_in[4];
    const float* ksc   = (const float*)d_in[5];
    const float* Wout  = (const float*)d_in[6];
    const float* ln2g  = (const float*)d_in[7];
    const float* ln2b  = (const float*)d_in[8];
    const float* W1    = (const float*)d_in[9];
    const float* b1    = (const float*)d_in[10];
    const float* W2    = (const float*)d_in[11];
    const float* b2    = (const float*)d_in[12];
    float* out = (float*)d_out;

    float *ph, *pqkv, *po, *px1, *pg;
    float *pWqkvc, *pWoutc, *pW1i, *pW2p, *pb1i;
    cudaGetSymbolAddress((void**)&ph,     g_h);
    cudaGetSymbolAddress((void**)&pqkv,   g_qkv);
    cudaGetSymbolAddress((void**)&po,     g_o);
    cudaGetSymbolAddress((void**)&px1,    g_x1);
    cudaGetSymbolAddress((void**)&pg,     g_gate);
    cudaGetSymbolAddress((void**)&pWqkvc, g_Wqkvc);
    cudaGetSymbolAddress((void**)&pWoutc, g_Woutc);
    cudaGetSymbolAddress((void**)&pW1i,   g_W1i);
    cudaGetSymbolAddress((void**)&pW2p,   g_W2p);
    cudaGetSymbolAddress((void**)&pb1i,   g_b1i);

    cudaFuncSetAttribute(gemm_mma<0>, cudaFuncAttributeMaxDynamicSharedMemorySize, GEMM_SMEM);
    cudaFuncSetAttribute(gemm_mma<1>, cudaFuncAttributeMaxDynamicSharedMemorySize, GEMM_SMEM);
    cudaFuncSetAttribute(gemm_mma<2>, cudaFuncAttributeMaxDynamicSharedMemorySize, GEMM_SMEM);
    cudaFuncSetAttribute(gemm_mma<3>, cudaFuncAttributeMaxDynamicSharedMemorySize, GEMM_SMEM);

    // 0) weight prep (tf32 pre-round; W1 interleave; W2 zero-pad; b1 interleave)
    {
        long n;
        n = (long)DMODEL * QKVN;
        cvt_kernel<<<(int)((n + 255) / 256), 256>>>(Wqkv, pWqkvc, (int)n);
        n = (long)DMODEL * DMODEL;
        cvt_kernel<<<(int)((n + 255) / 256), 256>>>(Wout, pWoutc, (int)n);
        n = (long)DMODEL * HID2P;
        cvt_w1i_kernel<<<(int)((n + 255) / 256), 256>>>(W1);
        n = (long)KFF2 * DMODEL;
        cvt_w2p_kernel<<<(int)((n + 255) / 256), 256>>>(W2);
        b1i_kernel<<<(HID2P + 255) / 256, 256>>>(b1);
    }

    // 1) LN1
    ln_kernel<<<BNROWS, 256>>>(x, ln1g, ln1b, ph);
    // 2) QKV GEMM: 16384 x 1536 x 512
    gemm_mma<0><<<dim3(QKVN / 256, BNROWS / 128), 256, GEMM_SMEM>>>(
        ph, pWqkvc, nullptr, nullptr, pqkv, QKVN, DMODEL, DMODEL, QKVN, QKVN);
    // 3) split + l2norm + rotary xpos
    qkv_rotary_kernel<<<(BATCH * SEQ * NH) / 4, 128>>>(qsc, ksc);
    // 4) tensor-core local attention
    attn_kernel<<<dim3(SEQ / 128, BHEADS), 256>>>();
    // 5) out projection + residual: 16384 x 512 x 512
    gemm_mma<1><<<dim3(DMODEL / 256, BNROWS / 128), 256, GEMM_SMEM>>>(
        po, pWoutc, nullptr, x, px1, DMODEL, DMODEL, DMODEL, DMODEL, DMODEL);
    // 6) LN2
    ln_kernel<<<BNROWS, 256>>>(px1, ln2g, ln2b, ph);
    // 7) FF1 + fused geglu: 16384 x 2816(interleaved) x 512 -> gate (1408 cols)
    gemm_mma<2><<<dim3(HID2P / 256, BNROWS / 128), 256, GEMM_SMEM>>>(
        ph, pW1i, pb1i, nullptr, pg, HID2P, DMODEL, DMODEL, HID2P, KFF2);
    // 8) FF2 + b2 + residual -> out: 16384 x 512 x 1408(zero-padded K)
    gemm_mma<3><<<dim3(DMODEL / 256, BNROWS / 128), 256, GEMM_SMEM>>>(
        pg, pW2p, b2, px1, out, DMODEL, KFF2, KFF2, DMODEL, DMODEL);
}

// round 8
// speedup vs baseline: 1.4834x; 1.4834x over previous
#include <cuda_runtime.h>
#include <cuda_bf16.h>
#include <math.h>
#include <stdint.h>

// ---------------- problem constants ----------------
#define BATCH   2
#define SEQ     8192
#define DMODEL  512
#define NH      8
#define DH      64
#define BHEADS  16
#define BNROWS  16384
#define QKVN    1536
#define HID     1365
#define HID2    2730
#define HID2P   2816   // FF1 N (interleaved a/gate) padded to mult of 128
#define KFF2    1408   // FF2 K padded to mult of 32 (= HID2P/2)
#define WSIZE   512

// ---------------- scratch buffers ----------------
__device__ __nv_bfloat16 g_h   [(size_t)BNROWS * DMODEL];
__device__ float         g_qkv [(size_t)BNROWS * QKVN];
__device__ float         g_q   [(size_t)BHEADS * SEQ * DH];
__device__ float         g_k   [(size_t)BHEADS * SEQ * DH];
__device__ float         g_v   [(size_t)BHEADS * SEQ * DH];
__device__ __nv_bfloat16 g_o   [(size_t)BNROWS * DMODEL];
__device__ float         g_x1  [(size_t)BNROWS * DMODEL];
__device__ __nv_bfloat16 g_gate[(size_t)BNROWS * KFF2];
__device__ __nv_bfloat16 g_WqkvT[(size_t)QKVN * DMODEL];   // [N][K]
__device__ __nv_bfloat16 g_WoutT[(size_t)DMODEL * DMODEL];
__device__ __nv_bfloat16 g_W1iT [(size_t)HID2P * DMODEL];  // interleaved a/gate rows
__device__ __nv_bfloat16 g_W2T  [(size_t)DMODEL * KFF2];   // cols >= HID zero
__device__ float         g_b1i  [HID2P];

// ---------------- helpers ----------------
__device__ __forceinline__ unsigned f2tf32(float f) {
    unsigned u;
    asm("cvt.rna.tf32.f32 %0, %1;" : "=r"(u) : "f"(f));
    return u;
}
__device__ __forceinline__ float tf32r(float f) { return __uint_as_float(f2tf32(f)); }
__device__ __forceinline__ float ex2f(float x) {
    float y;
    asm("ex2.approx.f32 %0, %1;" : "=f"(y) : "f"(x));
    return y;
}
__device__ __forceinline__ void mma_tf32(float c[4], const unsigned a[4], const unsigned b[2]) {
    asm volatile(
        "mma.sync.aligned.m16n8k8.row.col.f32.tf32.tf32.f32 "
        "{%0,%1,%2,%3}, {%4,%5,%6,%7}, {%8,%9}, {%0,%1,%2,%3};"
        : "+f"(c[0]), "+f"(c[1]), "+f"(c[2]), "+f"(c[3])
        : "r"(a[0]), "r"(a[1]), "r"(a[2]), "r"(a[3]), "r"(b[0]), "r"(b[1]));
}
__device__ __forceinline__ void mma_bf16(float c[4], const unsigned a[4], const unsigned b[2]) {
    asm volatile(
        "mma.sync.aligned.m16n8k16.row.col.f32.bf16.bf16.f32 "
        "{%0,%1,%2,%3}, {%4,%5,%6,%7}, {%8,%9}, {%0,%1,%2,%3};"
        : "+f"(c[0]), "+f"(c[1]), "+f"(c[2]), "+f"(c[3])
        : "r"(a[0]), "r"(a[1]), "r"(a[2]), "r"(a[3]), "r"(b[0]), "r"(b[1]));
}
__device__ __forceinline__ void cp16(const void* s, const void* g) {
    unsigned sa = (unsigned)__cvta_generic_to_shared(s);
    asm volatile("cp.async.cg.shared.global [%0], [%1], 16;" :: "r"(sa), "l"(g));
}
__device__ __forceinline__ void cp_commit() { asm volatile("cp.async.commit_group;"); }
template<int NN> __device__ __forceinline__ void cp_wait() {
    asm volatile("cp.async.wait_group %0;" :: "n"(NN));
}

// ---------------- weight prep: tiled transpose fp32 -> bf16 [N][K] ----------------
// dst rows cover grid.x*32 (padded N), cols grid.y*32 (padded K = Kpad).
// REMAP: column j of the logical [K][HID2] source is (j>>1)+(j&1)*HID (geglu interleave).
template<bool REMAP>
__global__ void transpose_bf16_k(const float* __restrict__ src, __nv_bfloat16* __restrict__ dst,
                                 int Ksrc, int Nsrc, int Kpad)
{
    __shared__ float t[32][33];
    int n0 = blockIdx.x * 32, k0 = blockIdx.y * 32;
    int x = threadIdx.x, y = threadIdx.y;   // 32 x 8
    #pragma unroll
    for (int i = 0; i < 32; i += 8) {
        int k = k0 + y + i, j = n0 + x;
        int c = REMAP ? ((j >> 1) + (j & 1) * HID) : j;
        int nlim = REMAP ? HID2 : Nsrc;
        t[y + i][x] = (k < Ksrc && j < nlim) ? src[(size_t)k * Nsrc + c] : 0.0f;
    }
    __syncthreads();
    #pragma unroll
    for (int i = 0; i < 32; i += 8) {
        int n = n0 + y + i, k = k0 + x;
        dst[(size_t)n * Kpad + k] = __float2bfloat16(t[x][y + i]);
    }
}
__global__ void b1i_kernel(const float* __restrict__ b1)
{
    int j = blockIdx.x * 256 + threadIdx.x;
    if (j < HID2P) g_b1i[j] = (j < HID2) ? b1[(j >> 1) + (j & 1) * HID] : 0.0f;
}

// ---------------- LayerNorm (emits bf16) ----------------
__global__ void ln_kernel(const float* __restrict__ x,
                          const float* __restrict__ gamma,
                          const float* __restrict__ beta,
                          __nv_bfloat16* __restrict__ out)
{
    int row = blockIdx.x;
    int tid = threadIdx.x;
    const float* xr = x + (size_t)row * DMODEL;
    float v0 = xr[tid];
    float v1 = xr[tid + 256];
    float s  = v0 + v1;
    float ss = v0 * v0 + v1 * v1;

    __shared__ float shs[8], shss[8];
    #pragma unroll
    for (int o = 16; o > 0; o >>= 1) {
        s  += __shfl_down_sync(0xffffffffu, s,  o);
        ss += __shfl_down_sync(0xffffffffu, ss, o);
    }
    if ((tid & 31) == 0) { shs[tid >> 5] = s; shss[tid >> 5] = ss; }
    __syncthreads();
    if (tid < 8) {
        s = shs[tid]; ss = shss[tid];
        #pragma unroll
        for (int o = 4; o > 0; o >>= 1) {
            s  += __shfl_down_sync(0xffu, s,  o);
            ss += __shfl_down_sync(0xffu, ss, o);
        }
        if (tid == 0) { shs[0] = s; shss[0] = ss; }
    }
    __syncthreads();
    float mean = shs[0]  * (1.0f / DMODEL);
    float var  = shss[0] * (1.0f / DMODEL) - mean * mean;
    float inv  = rsqrtf(var + 1e-5f);
    __nv_bfloat16* outr = out + (size_t)row * DMODEL;
    outr[tid]       = __float2bfloat16((v0 - mean) * inv * gamma[tid]       + beta[tid]);
    outr[tid + 256] = __float2bfloat16((v1 - mean) * inv * gamma[tid + 256] + beta[tid + 256]);
}

// ---------------- bf16 mma.sync GEMM, 128x128 CTA tile, 2 CTAs/SM ----------------
// C(MxN) = A(MxK, lda) @ BT(NxK, ldb)^T ; 256 threads, 8 warps (2m x 4n),
// warp tile 64x32, BK=32 (two m16n8k16 k-steps), 2-stage cp.async.
// M%128==0, N%128==0, K%32==0, lda/ldb mult of 8 (16B rows).
// MODE: 0 plain f32 out; 1 +res; 2 +bias, geglu pair -> bf16 half-width; 3 +bias+res
template<int MODE>
__global__ void __launch_bounds__(256, 2)
gemm_bf16(const __nv_bfloat16* __restrict__ A, const __nv_bfloat16* __restrict__ BT,
          const float* __restrict__ bias, const float* __restrict__ res,
          float* __restrict__ C, int K, int lda, int ldb, int ldc)
{
    __shared__ __nv_bfloat16 As[2][128][40];
    __shared__ __nv_bfloat16 Bs[2][128][40];

    int tid  = threadIdx.x;
    int lane = tid & 31;
    int wid  = tid >> 5;
    int g  = lane >> 2;
    int tg = lane & 3;
    int wm = (wid & 1) * 64;
    int wn = (wid >> 1) * 32;
    int m0 = blockIdx.y * 128, n0 = blockIdx.x * 128;

    float c[4][4][4];
    #pragma unroll
    for (int i = 0; i < 4; i++)
        #pragma unroll
        for (int j = 0; j < 4; j++)
            #pragma unroll
            for (int l = 0; l < 4; l++) c[i][j][l] = 0.0f;

    int T = K >> 5;
    // stage tile 0
    #pragma unroll
    for (int i = 0; i < 2; i++) {
        int idx = i * 256 + tid;
        int row = idx >> 2, c8 = (idx & 3) * 8;
        cp16(&As[0][row][c8], A + (size_t)(m0 + row) * lda + c8);
        cp16(&Bs[0][row][c8], BT + (size_t)(n0 + row) * ldb + c8);
    }
    cp_commit();

    for (int kt = 0; kt < T; kt++) {
        int buf = kt & 1;
        if (kt + 1 < T) {
            int k0 = (kt + 1) * 32;
            #pragma unroll
            for (int i = 0; i < 2; i++) {
                int idx = i * 256 + tid;
                int row = idx >> 2, c8 = (idx & 3) * 8;
                cp16(&As[buf ^ 1][row][c8], A + (size_t)(m0 + row) * lda + k0 + c8);
                cp16(&Bs[buf ^ 1][row][c8], BT + (size_t)(n0 + row) * ldb + k0 + c8);
            }
            cp_commit();
            cp_wait<1>();
        } else {
            cp_wait<0>();
        }
        __syncthreads();

        #pragma unroll
        for (int ks = 0; ks < 2; ks++) {
            int colk = ks * 16 + 2 * tg;
            unsigned a[4][4], b[4][2];
            #pragma unroll
            for (int mf = 0; mf < 4; mf++) {
                int row = wm + mf * 16 + g;
                a[mf][0] = *(const unsigned*)&As[buf][row][colk];
                a[mf][1] = *(const unsigned*)&As[buf][row + 8][colk];
                a[mf][2] = *(const unsigned*)&As[buf][row][colk + 8];
                a[mf][3] = *(const unsigned*)&As[buf][row + 8][colk + 8];
            }
            #pragma unroll
            for (int nf = 0; nf < 4; nf++) {
                int n = wn + nf * 8 + g;
                b[nf][0] = *(const unsigned*)&Bs[buf][n][colk];
                b[nf][1] = *(const unsigned*)&Bs[buf][n][colk + 8];
            }
            #pragma unroll
            for (int mf = 0; mf < 4; mf++)
                #pragma unroll
                for (int nf = 0; nf < 4; nf++)
                    mma_bf16(c[mf][nf], a[mf], b[nf]);
        }
        __syncthreads();
    }

    #pragma unroll
    for (int mf = 0; mf < 4; mf++) {
        int r0 = m0 + wm + mf * 16 + g;
        #pragma unroll
        for (int nf = 0; nf < 4; nf++) {
            int col = n0 + wn + nf * 8 + 2 * tg;
            #pragma unroll
            for (int half = 0; half < 2; half++) {
                int r = r0 + half * 8;
                float cx = c[mf][nf][half * 2];
                float cy = c[mf][nf][half * 2 + 1];
                if (MODE == 0) {
                    *(float2*)&C[(size_t)r * ldc + col] = make_float2(cx, cy);
                } else if (MODE == 1) {
                    float2 rr = *(const float2*)&res[(size_t)r * ldc + col];
                    *(float2*)&C[(size_t)r * ldc + col] =
                        make_float2(cx + rr.x, cy + rr.y);
                } else if (MODE == 2) {
                    float xa = cx + bias[col];
                    float yg = cy + bias[col + 1];
                    float ge = 0.5f * yg * (1.0f + erff(yg * 0.70710678118654752f));
                    ((__nv_bfloat16*)C)[(size_t)r * ldc + (col >> 1)] =
                        __float2bfloat16(xa * ge);
                } else {
                    float2 rr = *(const float2*)&res[(size_t)r * ldc + col];
                    *(float2*)&C[(size_t)r * ldc + col] =
                        make_float2(cx + bias[col] + rr.x,
                                    cy + bias[col + 1] + rr.y);
                }
            }
        }
    }
}

// ---------------- QKV split + l2norm + scale + rotary xpos ----------------
__global__ void qkv_rotary_kernel(const float* __restrict__ q_scale,
                                  const float* __restrict__ k_scale)
{
    int lane = threadIdx.x & 31;
    int warp = threadIdx.x >> 5;
    long task = (long)blockIdx.x * 4 + warp;
    int b = (int)(task / ((long)SEQ * NH));
    long rem = task - (long)b * SEQ * NH;
    int n = (int)(rem / NH);
    int h = (int)(rem - (long)n * NH);

    size_t base = ((size_t)b * SEQ + n) * QKVN + (size_t)h * DH;
    float q0 = g_qkv[base + lane],        q1 = g_qkv[base + 32 + lane];
    float k0 = g_qkv[base + 512 + lane],  k1 = g_qkv[base + 512 + 32 + lane];
    float v0 = g_qkv[base + 1024 + lane], v1 = g_qkv[base + 1024 + 32 + lane];

    float sq = q0 * q0 + q1 * q1;
    float sk = k0 * k0 + k1 * k1;
    #pragma unroll
    for (int o = 16; o > 0; o >>= 1) {
        sq += __shfl_xor_sync(0xffffffffu, sq, o);
        sk += __shfl_xor_sync(0xffffffffu, sk, o);
    }
    float qinv = 1.0f / fmaxf(sqrtf(sq), 1e-12f);
    float kinv = 1.0f / fmaxf(sqrtf(sk), 1e-12f);
    q0 = q0 * qinv * q_scale[lane];
    q1 = q1 * qinv * q_scale[lane + 32];
    k0 = k0 * kinv * k_scale[lane];
    k1 = k1 * kinv * k_scale[lane + 32];

    float t    = (float)n;
    float invf = exp2f((float)lane * (-13.287712379549449f / 32.0f));
    float fr   = t * invf;
    float cs = cosf(fr), sn = sinf(fr);
    float sv = (2.0f * (float)lane + 0.4f * 64.0f) / (1.4f * 64.0f);
    float pw = (t - (float)(SEQ / 2)) / (float)(WSIZE / 2);
    float xs = exp2f(pw * log2f(sv));
    float ixs = 1.0f / xs;

    const float QSC = 11.541560327111708f;   // 8 * log2(e)
    float qo0 = (q0 * cs - q1 * sn) * xs;
    float qo1 = (q1 * cs + q0 * sn) * xs;
    float ko0 = (k0 * cs - k1 * sn) * ixs;
    float ko1 = (k1 * cs + k0 * sn) * ixs;

    size_t obase = ((size_t)(b * NH + h) * SEQ + n) * DH;
    g_q[obase + lane]      = tf32r(QSC * qo0);
    g_q[obase + 32 + lane] = tf32r(QSC * qo1);
    g_k[obase + lane]      = tf32r(ko0);
    g_k[obase + 32 + lane] = tf32r(ko1);
    g_v[obase + lane]      = tf32r(v0);
    g_v[obase + 32 + lane] = tf32r(v1);
}

// ---------------- tensor-core local windowed attention (tf32, unchanged) ----------------
__device__ __forceinline__ void attn_stage(
    float (*Ks)[68], float (*Vs)[68],
    const float* kbase, const float* vbase, int kg0, int tid)
{
    #pragma unroll
    for (int i = 0; i < 4; i++) {
        int idx = i * 256 + tid;
        int kk = idx >> 4, d4 = idx & 15;
        size_t off = (size_t)(kg0 + kk) * DH + d4 * 4;
        cp16(&Ks[kk][d4 * 4], kbase + off);
        cp16(&Vs[kk][d4 * 4], vbase + off);
    }
    cp_commit();
}

__global__ void __launch_bounds__(256) attn_kernel()
{
    __shared__ float Ks[2][64][68];
    __shared__ float Vs[2][64][68];

    const int tid  = threadIdx.x;
    const int lane = tid & 31;
    const int wq   = tid >> 5;
    const int g    = lane >> 2;
    const int tg   = lane & 3;
    const int qb   = blockIdx.x;
    const int bh   = blockIdx.y;
    const int t0   = qb * 128;
    const int w    = t0 >> 9;
    const int rstart = (w > 0) ? 0 : ((512 - (t0 & 511)) >> 6);

    unsigned qf[8][4];
    {
        const float* qb0 = g_q + ((size_t)bh * SEQ + t0 + wq * 16) * DH;
        #pragma unroll
        for (int kc = 0; kc < 8; kc++) {
            qf[kc][0] = __float_as_uint(qb0[(size_t)g * DH + kc * 8 + tg]);
            qf[kc][1] = __float_as_uint(qb0[(size_t)(g + 8) * DH + kc * 8 + tg]);
            qf[kc][2] = __float_as_uint(qb0[(size_t)g * DH + kc * 8 + tg + 4]);
            qf[kc][3] = __float_as_uint(qb0[(size_t)(g + 8) * DH + kc * 8 + tg + 4]);
        }
    }

    float o[8][4];
    #pragma unroll
    for (int i = 0; i < 8; i++)
        #pragma unroll
        for (int j = 0; j < 4; j++) o[i][j] = 0.0f;
    float d0 = 0.0f, d1 = 0.0f;

    const float* kbase = g_k + (size_t)bh * SEQ * DH;
    const float* vbase = g_v + (size_t)bh * SEQ * DH;

    attn_stage(Ks[0], Vs[0], kbase, vbase, t0 - 512 + 64 * rstart, tid);

    const int q0r = wq * 16 + g;

    for (int r = rstart; r <= 9; r++) {
        int buf = (r - rstart) & 1;
        if (r < 9) {
            attn_stage(Ks[buf ^ 1], Vs[buf ^ 1], kbase, vbase,
                       t0 - 512 + 64 * (r + 1), tid);
            cp_wait<1>();
        } else {
            cp_wait<0>();
        }
        __syncthreads();

        float s[8][4];
        #pragma unroll
        for (int i = 0; i < 8; i++)
            #pragma unroll
            for (int j = 0; j < 4; j++) s[i][j] = 0.0f;

        #pragma unroll
        for (int kc = 0; kc < 8; kc++) {
            #pragma unroll
            for (int nf = 0; nf < 8; nf++) {
                unsigned b[2];
                b[0] = __float_as_uint(Ks[buf][nf * 8 + g][kc * 8 + tg]);
                b[1] = __float_as_uint(Ks[buf][nf * 8 + g][kc * 8 + tg + 4]);
                mma_tf32(s[nf], qf[kc], b);
            }
        }

        float p[8][4];
        #pragma unroll
        for (int nf = 0; nf < 8; nf++) {
            int j0  = nf * 8 + 2 * tg;
            int jr0 = 64 * r - 512 + j0;
            int jr1 = jr0 + 1;
            bool ok0 = (jr0 <= q0r)     && (jr0 >= q0r - 512);
            bool ok1 = (jr1 <= q0r)     && (jr1 >= q0r - 512);
            bool ok2 = (jr0 <= q0r + 8) && (jr0 >= q0r - 504);
            bool ok3 = (jr1 <= q0r + 8) && (jr1 >= q0r - 504);
            p[nf][0] = ok0 ? ex2f(s[nf][0]) : 0.0f;
            p[nf][1] = ok1 ? ex2f(s[nf][1]) : 0.0f;
            p[nf][2] = ok2 ? ex2f(s[nf][2]) : 0.0f;
            p[nf][3] = ok3 ? ex2f(s[nf][3]) : 0.0f;
            d0 += p[nf][0] + p[nf][1];
            d1 += p[nf][2] + p[nf][3];
        }

        #pragma unroll
        for (int kc = 0; kc < 8; kc++) {
            unsigned a[4];
            a[0] = f2tf32(p[kc][0]);
            a[1] = f2tf32(p[kc][2]);
            a[2] = f2tf32(p[kc][1]);
            a[3] = f2tf32(p[kc][3]);
            #pragma unroll
            for (int nf = 0; nf < 8; nf++) {
                unsigned b[2];
                b[0] = __float_as_uint(Vs[buf][kc * 8 + 2 * tg][nf * 8 + g]);
                b[1] = __float_as_uint(Vs[buf][kc * 8 + 2 * tg + 1][nf * 8 + g]);
                mma_tf32(o[nf], a, b);
            }
        }
        __syncthreads();
    }

    d0 += __shfl_xor_sync(0xffffffffu, d0, 1);
    d0 += __shfl_xor_sync(0xffffffffu, d0, 2);
    d1 += __shfl_xor_sync(0xffffffffu, d1, 1);
    d1 += __shfl_xor_sync(0xffffffffu, d1, 2);
    float i0 = 1.0f / d0, i1 = 1.0f / d1;

    int b = bh >> 3, h = bh & 7;
    int row0 = t0 + wq * 16 + g;
    __nv_bfloat16* ob = g_o + (size_t)b * SEQ * DMODEL + h * DH;
    #pragma unroll
    for (int nf = 0; nf < 8; nf++) {
        int col = nf * 8 + 2 * tg;
        __nv_bfloat162 lo, hi;
        lo.x = __float2bfloat16(o[nf][0] * i0);
        lo.y = __float2bfloat16(o[nf][1] * i0);
        hi.x = __float2bfloat16(o[nf][2] * i1);
        hi.y = __float2bfloat16(o[nf][3] * i1);
        *(__nv_bfloat162*)&ob[(size_t)row0 * DMODEL + col]       = lo;
        *(__nv_bfloat162*)&ob[(size_t)(row0 + 8) * DMODEL + col] = hi;
    }
}

// ---------------- launch ----------------
extern "C" void kernel_launch(void* const* d_in, const int* in_sizes, int n_in,
                              void* d_out, int out_size)
{
    const float* x     = (const float*)d_in[0];
    const float* ln1g  = (const float*)d_in[1];
    const float* ln1b  = (const float*)d_in[2];
    const float* Wqkv  = (const float*)d_in[3];
    const float* qsc   = (const float*)d_in[4];
    const float* ksc   = (const float*)d_in[5];
    const float* Wout  = (const float*)d_in[6];
    const float* ln2g  = (const float*)d_in[7];
    const float* ln2b  = (const float*)d_in[8];
    const float* W1    = (const float*)d_in[9];
    const float* b1    = (const float*)d_in[10];
    const float* W2    = (const float*)d_in[11];
    const float* b2    = (const float*)d_in[12];
    float* out = (float*)d_out;

    __nv_bfloat16 *ph, *po, *pg, *pWqkvT, *pWoutT, *pW1iT, *pW2T;
    float *pqkv, *px1, *pb1i;
    cudaGetSymbolAddress((void**)&ph,     g_h);
    cudaGetSymbolAddress((void**)&pqkv,   g_qkv);
    cudaGetSymbolAddress((void**)&po,     g_o);
    cudaGetSymbolAddress((void**)&px1,    g_x1);
    cudaGetSymbolAddress((void**)&pg,     g_gate);
    cudaGetSymbolAddress((void**)&pWqkvT, g_WqkvT);
    cudaGetSymbolAddress((void**)&pWoutT, g_WoutT);
    cudaGetSymbolAddress((void**)&pW1iT,  g_W1iT);
    cudaGetSymbolAddress((void**)&pW2T,   g_W2T);
    cudaGetSymbolAddress((void**)&pb1i,   g_b1i);

    // 0) weight prep: bf16 transposes to [N][K] (+geglu interleave, +pads)
    {
        dim3 blk(32, 8);
        transpose_bf16_k<false><<<dim3(QKVN / 32, DMODEL / 32), blk>>>(
            Wqkv, pWqkvT, DMODEL, QKVN, DMODEL);
        transpose_bf16_k<false><<<dim3(DMODEL / 32, DMODEL / 32), blk>>>(
            Wout, pWoutT, DMODEL, DMODEL, DMODEL);
        transpose_bf16_k<true><<<dim3(HID2P / 32, DMODEL / 32), blk>>>(
            W1, pW1iT, DMODEL, HID2, DMODEL);
        transpose_bf16_k<false><<<dim3(DMODEL / 32, KFF2 / 32), blk>>>(
            W2, pW2T, HID, DMODEL, KFF2);
        b1i_kernel<<<(HID2P + 255) / 256, 256>>>(b1);
    }

    // 1) LN1 -> h (bf16)
    ln_kernel<<<BNROWS, 256>>>(x, ln1g, ln1b, ph);
    // 2) QKV GEMM: 16384 x 1536 x 512 -> qkv (fp32)
    gemm_bf16<0><<<dim3(QKVN / 128, BNROWS / 128), 256>>>(
        ph, pWqkvT, nullptr, nullptr, pqkv, DMODEL, DMODEL, DMODEL, QKVN);
    // 3) split + l2norm + rotary xpos (tf32 q/k/v)
    qkv_rotary_kernel<<<(BATCH * SEQ * NH) / 4, 128>>>(qsc, ksc);
    // 4) tensor-core local attention -> o (bf16)
    attn_kernel<<<dim3(SEQ / 128, BHEADS), 256>>>();
    // 5) out projection + residual: 16384 x 512 x 512 -> x1 (fp32)
    gemm_bf16<1><<<dim3(DMODEL / 128, BNROWS / 128), 256>>>(
        po, pWoutT, nullptr, x, px1, DMODEL, DMODEL, DMODEL, DMODEL);
    // 6) LN2 -> h (bf16)
    ln_kernel<<<BNROWS, 256>>>(px1, ln2g, ln2b, ph);
    // 7) FF1 + fused geglu: 16384 x 2816 x 512 -> gate (bf16, 1408 cols)
    gemm_bf16<2><<<dim3(HID2P / 128, BNROWS / 128), 256>>>(
        ph, pW1iT, pb1i, nullptr, (float*)pg, DMODEL, DMODEL, DMODEL, KFF2);
    // 8) FF2 + b2 + residual -> out: 16384 x 512 x 1408
    gemm_bf16<3><<<dim3(DMODEL / 128, BNROWS / 128), 256>>>(
        pg, pW2T, b2, px1, out, KFF2, KFF2, KFF2, DMODEL);
}

// round 9
// speedup vs baseline: 1.5427x; 1.0400x over previous
#include <cuda_runtime.h>
#include <cuda_bf16.h>
#include <math.h>
#include <stdint.h>

// ---------------- problem constants ----------------
#define BATCH   2
#define SEQ     8192
#define DMODEL  512
#define NH      8
#define DH      64
#define BHEADS  16
#define BNROWS  16384
#define QKVN    1536
#define HID     1365
#define HID2    2730
#define HID2P   2816
#define KFF2    1408
#define WSIZE   512

// ---------------- scratch buffers ----------------
__device__ __nv_bfloat16 g_h   [(size_t)BNROWS * DMODEL];
__device__ __nv_bfloat16 g_qkvb[(size_t)BNROWS * QKVN];
__device__ __nv_bfloat16 g_q   [(size_t)BHEADS * SEQ * DH];   // pre-scaled by 8*log2e
__device__ __nv_bfloat16 g_k   [(size_t)BHEADS * SEQ * DH];
__device__ float         g_v   [(size_t)BHEADS * SEQ * DH];   // tf32-rounded
__device__ __nv_bfloat16 g_o   [(size_t)BNROWS * DMODEL];
__device__ float         g_x1  [(size_t)BNROWS * DMODEL];
__device__ __nv_bfloat16 g_gate[(size_t)BNROWS * KFF2];
__device__ __nv_bfloat16 g_WqkvT[(size_t)QKVN * DMODEL];
__device__ __nv_bfloat16 g_WoutT[(size_t)DMODEL * DMODEL];
__device__ __nv_bfloat16 g_W1iT [(size_t)HID2P * DMODEL];
__device__ __nv_bfloat16 g_W2T  [(size_t)DMODEL * KFF2];
__device__ float         g_b1i  [HID2P];

// ---------------- helpers ----------------
__device__ __forceinline__ unsigned f2tf32(float f) {
    unsigned u;
    asm("cvt.rna.tf32.f32 %0, %1;" : "=r"(u) : "f"(f));
    return u;
}
__device__ __forceinline__ float tf32r(float f) { return __uint_as_float(f2tf32(f)); }
__device__ __forceinline__ float ex2f(float x) {
    float y;
    asm("ex2.approx.f32 %0, %1;" : "=f"(y) : "f"(x));
    return y;
}
__device__ __forceinline__ void mma_tf32(float c[4], const unsigned a[4], const unsigned b[2]) {
    asm volatile(
        "mma.sync.aligned.m16n8k8.row.col.f32.tf32.tf32.f32 "
        "{%0,%1,%2,%3}, {%4,%5,%6,%7}, {%8,%9}, {%0,%1,%2,%3};"
        : "+f"(c[0]), "+f"(c[1]), "+f"(c[2]), "+f"(c[3])
        : "r"(a[0]), "r"(a[1]), "r"(a[2]), "r"(a[3]), "r"(b[0]), "r"(b[1]));
}
__device__ __forceinline__ void mma_bf16(float c[4], const unsigned a[4], const unsigned b[2]) {
    asm volatile(
        "mma.sync.aligned.m16n8k16.row.col.f32.bf16.bf16.f32 "
        "{%0,%1,%2,%3}, {%4,%5,%6,%7}, {%8,%9}, {%0,%1,%2,%3};"
        : "+f"(c[0]), "+f"(c[1]), "+f"(c[2]), "+f"(c[3])
        : "r"(a[0]), "r"(a[1]), "r"(a[2]), "r"(a[3]), "r"(b[0]), "r"(b[1]));
}
__device__ __forceinline__ void cp16(const void* s, const void* g) {
    unsigned sa = (unsigned)__cvta_generic_to_shared(s);
    asm volatile("cp.async.cg.shared.global [%0], [%1], 16;" :: "r"(sa), "l"(g));
}
__device__ __forceinline__ void cp_commit() { asm volatile("cp.async.commit_group;"); }
template<int NN> __device__ __forceinline__ void cp_wait() {
    asm volatile("cp.async.wait_group %0;" :: "n"(NN));
}

// ---------------- weight prep ----------------
template<bool REMAP>
__global__ void transpose_bf16_k(const float* __restrict__ src, __nv_bfloat16* __restrict__ dst,
                                 int Ksrc, int Nsrc, int Kpad)
{
    __shared__ float t[32][33];
    int n0 = blockIdx.x * 32, k0 = blockIdx.y * 32;
    int x = threadIdx.x, y = threadIdx.y;
    #pragma unroll
    for (int i = 0; i < 32; i += 8) {
        int k = k0 + y + i, j = n0 + x;
        int c = REMAP ? ((j >> 1) + (j & 1) * HID) : j;
        int nlim = REMAP ? HID2 : Nsrc;
        t[y + i][x] = (k < Ksrc && j < nlim) ? src[(size_t)k * Nsrc + c] : 0.0f;
    }
    __syncthreads();
    #pragma unroll
    for (int i = 0; i < 32; i += 8) {
        int n = n0 + y + i, k = k0 + x;
        dst[(size_t)n * Kpad + k] = __float2bfloat16(t[x][y + i]);
    }
}
__global__ void b1i_kernel(const float* __restrict__ b1)
{
    int j = blockIdx.x * 256 + threadIdx.x;
    if (j < HID2P) g_b1i[j] = (j < HID2) ? b1[(j >> 1) + (j & 1) * HID] : 0.0f;
}

// ---------------- LayerNorm (emits bf16) ----------------
__global__ void ln_kernel(const float* __restrict__ x,
                          const float* __restrict__ gamma,
                          const float* __restrict__ beta,
                          __nv_bfloat16* __restrict__ out)
{
    int row = blockIdx.x;
    int tid = threadIdx.x;
    const float* xr = x + (size_t)row * DMODEL;
    float v0 = xr[tid];
    float v1 = xr[tid + 256];
    float s  = v0 + v1;
    float ss = v0 * v0 + v1 * v1;

    __shared__ float shs[8], shss[8];
    #pragma unroll
    for (int o = 16; o > 0; o >>= 1) {
        s  += __shfl_down_sync(0xffffffffu, s,  o);
        ss += __shfl_down_sync(0xffffffffu, ss, o);
    }
    if ((tid & 31) == 0) { shs[tid >> 5] = s; shss[tid >> 5] = ss; }
    __syncthreads();
    if (tid < 8) {
        s = shs[tid]; ss = shss[tid];
        #pragma unroll
        for (int o = 4; o > 0; o >>= 1) {
            s  += __shfl_down_sync(0xffu, s,  o);
            ss += __shfl_down_sync(0xffu, ss, o);
        }
        if (tid == 0) { shs[0] = s; shss[0] = ss; }
    }
    __syncthreads();
    float mean = shs[0]  * (1.0f / DMODEL);
    float var  = shss[0] * (1.0f / DMODEL) - mean * mean;
    float inv  = rsqrtf(var + 1e-5f);
    __nv_bfloat16* outr = out + (size_t)row * DMODEL;
    outr[tid]       = __float2bfloat16((v0 - mean) * inv * gamma[tid]       + beta[tid]);
    outr[tid + 256] = __float2bfloat16((v1 - mean) * inv * gamma[tid + 256] + beta[tid + 256]);
}

// ---------------- bf16 mma.sync GEMM, 128x128 tile, 3-stage pipeline ----------------
// MODE: 0 f32 out; 1 +res; 2 +bias geglu->bf16 half-width; 3 +bias+res; 4 bf16 out
#define GSTG (128 * 40)
#define GEMM_SMEM (6 * GSTG * 2)   // 3 stages x (A+B) x bf16

template<int MODE>
__global__ void __launch_bounds__(256, 2)
gemm_bf16(const __nv_bfloat16* __restrict__ A, const __nv_bfloat16* __restrict__ BT,
          const float* __restrict__ bias, const float* __restrict__ res,
          float* __restrict__ C, int K, int lda, int ldb, int ldc)
{
    extern __shared__ __nv_bfloat16 smem[];
    __nv_bfloat16 (*As)[40] = (__nv_bfloat16(*)[40])smem;
    __nv_bfloat16 (*Bs)[40] = (__nv_bfloat16(*)[40])(smem + 3 * GSTG);

    int tid  = threadIdx.x;
    int lane = tid & 31;
    int wid  = tid >> 5;
    int g  = lane >> 2;
    int tg = lane & 3;
    int wm = (wid & 1) * 64;
    int wn = (wid >> 1) * 32;
    int m0 = blockIdx.y * 128, n0 = blockIdx.x * 128;

    float c[4][4][4];
    #pragma unroll
    for (int i = 0; i < 4; i++)
        #pragma unroll
        for (int j = 0; j < 4; j++)
            #pragma unroll
            for (int l = 0; l < 4; l++) c[i][j][l] = 0.0f;

    int T = K >> 5;

    auto stage = [&](int st, int k0) {
        #pragma unroll
        for (int i = 0; i < 2; i++) {
            int idx = i * 256 + tid;
            int row = idx >> 2, c8 = (idx & 3) * 8;
            cp16(&As[st * 128 + row][c8], A + (size_t)(m0 + row) * lda + k0 + c8);
            cp16(&Bs[st * 128 + row][c8], BT + (size_t)(n0 + row) * ldb + k0 + c8);
        }
        cp_commit();
    };

    stage(0, 0);
    if (T > 1) stage(1, 32);

    for (int kt = 0; kt < T; kt++) {
        if (kt + 1 < T) { cp_wait<1>(); } else { cp_wait<0>(); }
        __syncthreads();
        if (kt + 2 < T) stage((kt + 2) % 3, (kt + 2) * 32);

        int st = kt % 3;
        __nv_bfloat16 (*Ab)[40] = As + st * 128;
        __nv_bfloat16 (*Bb)[40] = Bs + st * 128;
        #pragma unroll
        for (int ks = 0; ks < 2; ks++) {
            int colk = ks * 16 + 2 * tg;
            unsigned a[4][4], b[4][2];
            #pragma unroll
            for (int mf = 0; mf < 4; mf++) {
                int row = wm + mf * 16 + g;
                a[mf][0] = *(const unsigned*)&Ab[row][colk];
                a[mf][1] = *(const unsigned*)&Ab[row + 8][colk];
                a[mf][2] = *(const unsigned*)&Ab[row][colk + 8];
                a[mf][3] = *(const unsigned*)&Ab[row + 8][colk + 8];
            }
            #pragma unroll
            for (int nf = 0; nf < 4; nf++) {
                int n = wn + nf * 8 + g;
                b[nf][0] = *(const unsigned*)&Bb[n][colk];
                b[nf][1] = *(const unsigned*)&Bb[n][colk + 8];
            }
            #pragma unroll
            for (int mf = 0; mf < 4; mf++)
                #pragma unroll
                for (int nf = 0; nf < 4; nf++)
                    mma_bf16(c[mf][nf], a[mf], b[nf]);
        }
    }

    #pragma unroll
    for (int mf = 0; mf < 4; mf++) {
        int r0 = m0 + wm + mf * 16 + g;
        #pragma unroll
        for (int nf = 0; nf < 4; nf++) {
            int col = n0 + wn + nf * 8 + 2 * tg;
            #pragma unroll
            for (int half = 0; half < 2; half++) {
                int r = r0 + half * 8;
                float cx = c[mf][nf][half * 2];
                float cy = c[mf][nf][half * 2 + 1];
                if (MODE == 0) {
                    *(float2*)&C[(size_t)r * ldc + col] = make_float2(cx, cy);
                } else if (MODE == 1) {
                    float2 rr = *(const float2*)&res[(size_t)r * ldc + col];
                    *(float2*)&C[(size_t)r * ldc + col] =
                        make_float2(cx + rr.x, cy + rr.y);
                } else if (MODE == 2) {
                    float xa = cx + bias[col];
                    float yg = cy + bias[col + 1];
                    float ge = 0.5f * yg * (1.0f + erff(yg * 0.70710678118654752f));
                    ((__nv_bfloat16*)C)[(size_t)r * ldc + (col >> 1)] =
                        __float2bfloat16(xa * ge);
                } else if (MODE == 3) {
                    float2 rr = *(const float2*)&res[(size_t)r * ldc + col];
                    *(float2*)&C[(size_t)r * ldc + col] =
                        make_float2(cx + bias[col] + rr.x,
                                    cy + bias[col + 1] + rr.y);
                } else {
                    __nv_bfloat162 o2;
                    o2.x = __float2bfloat16(cx);
                    o2.y = __float2bfloat16(cy);
                    *(__nv_bfloat162*)&((__nv_bfloat16*)C)[(size_t)r * ldc + col] = o2;
                }
            }
        }
    }
}

// ---------------- QKV split + l2norm + scale + rotary xpos ----------------
__global__ void qkv_rotary_kernel(const float* __restrict__ q_scale,
                                  const float* __restrict__ k_scale)
{
    int lane = threadIdx.x & 31;
    int warp = threadIdx.x >> 5;
    long task = (long)blockIdx.x * 4 + warp;
    int b = (int)(task / ((long)SEQ * NH));
    long rem = task - (long)b * SEQ * NH;
    int n = (int)(rem / NH);
    int h = (int)(rem - (long)n * NH);

    size_t base = ((size_t)b * SEQ + n) * QKVN + (size_t)h * DH;
    float q0 = __bfloat162float(g_qkvb[base + lane]);
    float q1 = __bfloat162float(g_qkvb[base + 32 + lane]);
    float k0 = __bfloat162float(g_qkvb[base + 512 + lane]);
    float k1 = __bfloat162float(g_qkvb[base + 512 + 32 + lane]);
    float v0 = __bfloat162float(g_qkvb[base + 1024 + lane]);
    float v1 = __bfloat162float(g_qkvb[base + 1024 + 32 + lane]);

    float sq = q0 * q0 + q1 * q1;
    float sk = k0 * k0 + k1 * k1;
    #pragma unroll
    for (int o = 16; o > 0; o >>= 1) {
        sq += __shfl_xor_sync(0xffffffffu, sq, o);
        sk += __shfl_xor_sync(0xffffffffu, sk, o);
    }
    float qinv = 1.0f / fmaxf(sqrtf(sq), 1e-12f);
    float kinv = 1.0f / fmaxf(sqrtf(sk), 1e-12f);
    q0 = q0 * qinv * q_scale[lane];
    q1 = q1 * qinv * q_scale[lane + 32];
    k0 = k0 * kinv * k_scale[lane];
    k1 = k1 * kinv * k_scale[lane + 32];

    float t    = (float)n;
    float invf = exp2f((float)lane * (-13.287712379549449f / 32.0f));
    float fr   = t * invf;
    float cs = cosf(fr), sn = sinf(fr);
    float sv = (2.0f * (float)lane + 0.4f * 64.0f) / (1.4f * 64.0f);
    float pw = (t - (float)(SEQ / 2)) / (float)(WSIZE / 2);
    float xs = exp2f(pw * log2f(sv));
    float ixs = 1.0f / xs;

    const float QSC = 11.541560327111708f;   // 8 * log2(e)
    float qo0 = (q0 * cs - q1 * sn) * xs;
    float qo1 = (q1 * cs + q0 * sn) * xs;
    float ko0 = (k0 * cs - k1 * sn) * ixs;
    float ko1 = (k1 * cs + k0 * sn) * ixs;

    size_t obase = ((size_t)(b * NH + h) * SEQ + n) * DH;
    g_q[obase + lane]      = __float2bfloat16(QSC * qo0);
    g_q[obase + 32 + lane] = __float2bfloat16(QSC * qo1);
    g_k[obase + lane]      = __float2bfloat16(ko0);
    g_k[obase + 32 + lane] = __float2bfloat16(ko1);
    g_v[obase + lane]      = tf32r(v0);
    g_v[obase + 32 + lane] = tf32r(v1);
}

// ---------------- local windowed attention: QK bf16 mma, PV tf32 mma ----------------
#define ATTN_KS_ROW 72
#define ATTN_VS_ROW 68
#define ATTN_SMEM (2 * 64 * ATTN_KS_ROW * 2 + 2 * 64 * ATTN_VS_ROW * 4)

__global__ void __launch_bounds__(256) attn_kernel()
{
    extern __shared__ char asmem[];
    __nv_bfloat16 (*Ks)[ATTN_KS_ROW] = (__nv_bfloat16(*)[ATTN_KS_ROW])asmem;
    float (*Vs)[ATTN_VS_ROW] = (float(*)[ATTN_VS_ROW])(asmem + 2 * 64 * ATTN_KS_ROW * 2);

    const int tid  = threadIdx.x;
    const int lane = tid & 31;
    const int wq   = tid >> 5;
    const int g    = lane >> 2;
    const int tg   = lane & 3;
    const int qb   = blockIdx.x;
    const int bh   = blockIdx.y;
    const int t0   = qb * 128;
    const int w    = t0 >> 9;
    const int rstart = (w > 0) ? 0 : ((512 - (t0 & 511)) >> 6);

    // Q fragments (bf16, pre-scaled): 4 k-steps of 16
    unsigned qf[4][4];
    {
        const __nv_bfloat16* qb0 = g_q + ((size_t)bh * SEQ + t0 + wq * 16) * DH;
        #pragma unroll
        for (int kc = 0; kc < 4; kc++) {
            qf[kc][0] = *(const unsigned*)&qb0[(size_t)g * DH + kc * 16 + 2 * tg];
            qf[kc][1] = *(const unsigned*)&qb0[(size_t)(g + 8) * DH + kc * 16 + 2 * tg];
            qf[kc][2] = *(const unsigned*)&qb0[(size_t)g * DH + kc * 16 + 2 * tg + 8];
            qf[kc][3] = *(const unsigned*)&qb0[(size_t)(g + 8) * DH + kc * 16 + 2 * tg + 8];
        }
    }

    float o[8][4];
    #pragma unroll
    for (int i = 0; i < 8; i++)
        #pragma unroll
        for (int j = 0; j < 4; j++) o[i][j] = 0.0f;
    float d0 = 0.0f, d1 = 0.0f;

    const __nv_bfloat16* kbase = g_k + (size_t)bh * SEQ * DH;
    const float* vbase = g_v + (size_t)bh * SEQ * DH;

    auto stage = [&](int buf, int kg0) {
        #pragma unroll
        for (int i = 0; i < 2; i++) {        // K: 64 rows x 64 bf16 (8 chunks/row)
            int idx = i * 256 + tid;
            int kk = idx >> 3, d8 = idx & 7;
            cp16(&Ks[buf * 64 + kk][d8 * 8], kbase + (size_t)(kg0 + kk) * DH + d8 * 8);
        }
        #pragma unroll
        for (int i = 0; i < 4; i++) {        // V: 64 rows x 64 f32 (16 chunks/row)
            int idx = i * 256 + tid;
            int kk = idx >> 4, d4 = idx & 15;
            cp16(&Vs[buf * 64 + kk][d4 * 4], vbase + (size_t)(kg0 + kk) * DH + d4 * 4);
        }
        cp_commit();
    };

    stage(0, t0 - 512 + 64 * rstart);

    const int q0r = wq * 16 + g;

    for (int r = rstart; r <= 9; r++) {
        int buf = (r - rstart) & 1;
        if (r < 9) {
            stage(buf ^ 1, t0 - 512 + 64 * (r + 1));
            cp_wait<1>();
        } else {
            cp_wait<0>();
        }
        __syncthreads();

        // S = Qscaled @ K^T (bf16)
        float s[8][4];
        #pragma unroll
        for (int i = 0; i < 8; i++)
            #pragma unroll
            for (int j = 0; j < 4; j++) s[i][j] = 0.0f;

        #pragma unroll
        for (int kc = 0; kc < 4; kc++) {
            #pragma unroll
            for (int nf = 0; nf < 8; nf++) {
                unsigned b[2];
                const __nv_bfloat16* kr = &Ks[buf * 64 + nf * 8 + g][kc * 16 + 2 * tg];
                b[0] = *(const unsigned*)kr;
                b[1] = *(const unsigned*)(kr + 8);
                mma_bf16(s[nf], qf[kc], b);
            }
        }

        // mask + exp2
        float p[8][4];
        #pragma unroll
        for (int nf = 0; nf < 8; nf++) {
            int j0  = nf * 8 + 2 * tg;
            int jr0 = 64 * r - 512 + j0;
            int jr1 = jr0 + 1;
            bool ok0 = (jr0 <= q0r)     && (jr0 >= q0r - 512);
            bool ok1 = (jr1 <= q0r)     && (jr1 >= q0r - 512);
            bool ok2 = (jr0 <= q0r + 8) && (jr0 >= q0r - 504);
            bool ok3 = (jr1 <= q0r + 8) && (jr1 >= q0r - 504);
            p[nf][0] = ok0 ? ex2f(s[nf][0]) : 0.0f;
            p[nf][1] = ok1 ? ex2f(s[nf][1]) : 0.0f;
            p[nf][2] = ok2 ? ex2f(s[nf][2]) : 0.0f;
            p[nf][3] = ok3 ? ex2f(s[nf][3]) : 0.0f;
            d0 += p[nf][0] + p[nf][1];
            d1 += p[nf][2] + p[nf][3];
        }

        // O += P @ V (tf32, consistent key relabeling)
        #pragma unroll
        for (int kc = 0; kc < 8; kc++) {
            unsigned a[4];
            a[0] = f2tf32(p[kc][0]);
            a[1] = f2tf32(p[kc][2]);
            a[2] = f2tf32(p[kc][1]);
            a[3] = f2tf32(p[kc][3]);
            #pragma unroll
            for (int nf = 0; nf < 8; nf++) {
                unsigned b[2];
                b[0] = __float_as_uint(Vs[buf * 64 + kc * 8 + 2 * tg][nf * 8 + g]);
                b[1] = __float_as_uint(Vs[buf * 64 + kc * 8 + 2 * tg + 1][nf * 8 + g]);
                mma_tf32(o[nf], a, b);
            }
        }
        __syncthreads();
    }

    d0 += __shfl_xor_sync(0xffffffffu, d0, 1);
    d0 += __shfl_xor_sync(0xffffffffu, d0, 2);
    d1 += __shfl_xor_sync(0xffffffffu, d1, 1);
    d1 += __shfl_xor_sync(0xffffffffu, d1, 2);
    float i0 = 1.0f / d0, i1 = 1.0f / d1;

    int b = bh >> 3, h = bh & 7;
    int row0 = t0 + wq * 16 + g;
    __nv_bfloat16* ob = g_o + (size_t)b * SEQ * DMODEL + h * DH;
    #pragma unroll
    for (int nf = 0; nf < 8; nf++) {
        int col = nf * 8 + 2 * tg;
        __nv_bfloat162 lo, hi;
        lo.x = __float2bfloat16(o[nf][0] * i0);
        lo.y = __float2bfloat16(o[nf][1] * i0);
        hi.x = __float2bfloat16(o[nf][2] * i1);
        hi.y = __float2bfloat16(o[nf][3] * i1);
        *(__nv_bfloat162*)&ob[(size_t)row0 * DMODEL + col]       = lo;
        *(__nv_bfloat162*)&ob[(size_t)(row0 + 8) * DMODEL + col] = hi;
    }
}

// ---------------- launch ----------------
extern "C" void kernel_launch(void* const* d_in, const int* in_sizes, int n_in,
                              void* d_out, int out_size)
{
    const float* x     = (const float*)d_in[0];
    const float* ln1g  = (const float*)d_in[1];
    const float* ln1b  = (const float*)d_in[2];
    const float* Wqkv  = (const float*)d_in[3];
    const float* qsc   = (const float*)d_in[4];
    const float* ksc   = (const float*)d_in[5];
    const float* Wout  = (const float*)d_in[6];
    const float* ln2g  = (const float*)d_in[7];
    const float* ln2b  = (const float*)d_in[8];
    const float* W1    = (const float*)d_in[9];
    const float* b1    = (const float*)d_in[10];
    const float* W2    = (const float*)d_in[11];
    const float* b2    = (const float*)d_in[12];
    float* out = (float*)d_out;

    __nv_bfloat16 *ph, *pqkvb, *po, *pg, *pWqkvT, *pWoutT, *pW1iT, *pW2T;
    float *px1, *pb1i;
    cudaGetSymbolAddress((void**)&ph,     g_h);
    cudaGetSymbolAddress((void**)&pqkvb,  g_qkvb);
    cudaGetSymbolAddress((void**)&po,     g_o);
    cudaGetSymbolAddress((void**)&px1,    g_x1);
    cudaGetSymbolAddress((void**)&pg,     g_gate);
    cudaGetSymbolAddress((void**)&pWqkvT, g_WqkvT);
    cudaGetSymbolAddress((void**)&pWoutT, g_WoutT);
    cudaGetSymbolAddress((void**)&pW1iT,  g_W1iT);
    cudaGetSymbolAddress((void**)&pW2T,   g_W2T);
    cudaGetSymbolAddress((void**)&pb1i,   g_b1i);

    cudaFuncSetAttribute(gemm_bf16<0>, cudaFuncAttributeMaxDynamicSharedMemorySize, GEMM_SMEM);
    cudaFuncSetAttribute(gemm_bf16<1>, cudaFuncAttributeMaxDynamicSharedMemorySize, GEMM_SMEM);
    cudaFuncSetAttribute(gemm_bf16<2>, cudaFuncAttributeMaxDynamicSharedMemorySize, GEMM_SMEM);
    cudaFuncSetAttribute(gemm_bf16<3>, cudaFuncAttributeMaxDynamicSharedMemorySize, GEMM_SMEM);
    cudaFuncSetAttribute(gemm_bf16<4>, cudaFuncAttributeMaxDynamicSharedMemorySize, GEMM_SMEM);
    cudaFuncSetAttribute(attn_kernel,  cudaFuncAttributeMaxDynamicSharedMemorySize, ATTN_SMEM);

    // 0) weight prep
    {
        dim3 blk(32, 8);
        transpose_bf16_k<false><<<dim3(QKVN / 32, DMODEL / 32), blk>>>(
            Wqkv, pWqkvT, DMODEL, QKVN, DMODEL);
        transpose_bf16_k<false><<<dim3(DMODEL / 32, DMODEL / 32), blk>>>(
            Wout, pWoutT, DMODEL, DMODEL, DMODEL);
        transpose_bf16_k<true><<<dim3(HID2P / 32, DMODEL / 32), blk>>>(
            W1, pW1iT, DMODEL, HID2, DMODEL);
        transpose_bf16_k<false><<<dim3(DMODEL / 32, KFF2 / 32), blk>>>(
            W2, pW2T, HID, DMODEL, KFF2);
        b1i_kernel<<<(HID2P + 255) / 256, 256>>>(b1);
    }

    // 1) LN1 -> h (bf16)
    ln_kernel<<<BNROWS, 256>>>(x, ln1g, ln1b, ph);
    // 2) QKV GEMM -> qkv (bf16)
    gemm_bf16<4><<<dim3(QKVN / 128, BNROWS / 128), 256, GEMM_SMEM>>>(
        ph, pWqkvT, nullptr, nullptr, (float*)pqkvb, DMODEL, DMODEL, DMODEL, QKVN);
    // 3) split + l2norm + rotary xpos -> q,k bf16; v tf32
    qkv_rotary_kernel<<<(BATCH * SEQ * NH) / 4, 128>>>(qsc, ksc);
    // 4) local attention -> o (bf16)
    attn_kernel<<<dim3(SEQ / 128, BHEADS), 256, ATTN_SMEM>>>();
    // 5) out projection + residual -> x1 (fp32)
    gemm_bf16<1><<<dim3(DMODEL / 128, BNROWS / 128), 256, GEMM_SMEM>>>(
        po, pWoutT, nullptr, x, px1, DMODEL, DMODEL, DMODEL, DMODEL);
    // 6) LN2 -> h (bf16)
    ln_kernel<<<BNROWS, 256>>>(px1, ln2g, ln2b, ph);
    // 7) FF1 + fused geglu -> gate (bf16)
    gemm_bf16<2><<<dim3(HID2P / 128, BNROWS / 128), 256, GEMM_SMEM>>>(
        ph, pW1iT, pb1i, nullptr, (float*)pg, DMODEL, DMODEL, DMODEL, KFF2);
    // 8) FF2 + b2 + residual -> out
    gemm_bf16<3><<<dim3(DMODEL / 128, BNROWS / 128), 256, GEMM_SMEM>>>(
        pg, pW2T, b2, px1, out, KFF2, KFF2, KFF2, DMODEL);
}

// round 10
// speedup vs baseline: 1.7296x; 1.1212x over previous
#include <cuda_runtime.h>
#include <cuda_bf16.h>
#include <math.h>
#include <stdint.h>

// ---------------- problem constants ----------------
#define BATCH   2
#define SEQ     8192
#define DMODEL  512
#define NH      8
#define DH      64
#define BHEADS  16
#define BNROWS  16384
#define QKVN    1536
#define HID     1365
#define HID2    2730
#define HID2P   2816
#define KFF2    1408
#define WSIZE   512

// ---------------- scratch buffers ----------------
__device__ __nv_bfloat16 g_h   [(size_t)BNROWS * DMODEL];
__device__ __nv_bfloat16 g_qkvb[(size_t)BNROWS * QKVN];
__device__ __nv_bfloat16 g_q   [(size_t)BHEADS * SEQ * DH];   // pre-scaled by 8*log2e
__device__ __nv_bfloat16 g_k   [(size_t)BHEADS * SEQ * DH];
__device__ __nv_bfloat16 g_v   [(size_t)BHEADS * SEQ * DH];
__device__ __nv_bfloat16 g_o   [(size_t)BNROWS * DMODEL];
__device__ float         g_x1  [(size_t)BNROWS * DMODEL];
__device__ __nv_bfloat16 g_gate[(size_t)BNROWS * KFF2];
__device__ __nv_bfloat16 g_WqkvT[(size_t)QKVN * DMODEL];
__device__ __nv_bfloat16 g_WoutT[(size_t)DMODEL * DMODEL];
__device__ __nv_bfloat16 g_W1iT [(size_t)HID2P * DMODEL];
__device__ __nv_bfloat16 g_W2T  [(size_t)DMODEL * KFF2];
__device__ float         g_b1i  [HID2P];

// ---------------- helpers ----------------
__device__ __forceinline__ float ex2f(float x) {
    float y;
    asm("ex2.approx.f32 %0, %1;" : "=f"(y) : "f"(x));
    return y;
}
__device__ __forceinline__ void mma_bf16(float c[4], const unsigned a[4], const unsigned b[2]) {
    asm volatile(
        "mma.sync.aligned.m16n8k16.row.col.f32.bf16.bf16.f32 "
        "{%0,%1,%2,%3}, {%4,%5,%6,%7}, {%8,%9}, {%0,%1,%2,%3};"
        : "+f"(c[0]), "+f"(c[1]), "+f"(c[2]), "+f"(c[3])
        : "r"(a[0]), "r"(a[1]), "r"(a[2]), "r"(a[3]), "r"(b[0]), "r"(b[1]));
}
__device__ __forceinline__ void ldsm_x4(unsigned r[4], uint32_t addr) {
    asm volatile("ldmatrix.sync.aligned.m8n8.x4.shared.b16 {%0,%1,%2,%3}, [%4];"
                 : "=r"(r[0]), "=r"(r[1]), "=r"(r[2]), "=r"(r[3]) : "r"(addr));
}
__device__ __forceinline__ void ldsm_x4_t(unsigned r[4], uint32_t addr) {
    asm volatile("ldmatrix.sync.aligned.m8n8.x4.trans.shared.b16 {%0,%1,%2,%3}, [%4];"
                 : "=r"(r[0]), "=r"(r[1]), "=r"(r[2]), "=r"(r[3]) : "r"(addr));
}
__device__ __forceinline__ unsigned packbf2(float lo, float hi) {
    unsigned d;
    asm("cvt.rn.bf16x2.f32 %0, %1, %2;" : "=r"(d) : "f"(hi), "f"(lo));
    return d;
}
__device__ __forceinline__ void cp16(const void* s, const void* g) {
    unsigned sa = (unsigned)__cvta_generic_to_shared(s);
    asm volatile("cp.async.cg.shared.global [%0], [%1], 16;" :: "r"(sa), "l"(g));
}
__device__ __forceinline__ void cp_commit() { asm volatile("cp.async.commit_group;"); }
template<int NN> __device__ __forceinline__ void cp_wait() {
    asm volatile("cp.async.wait_group %0;" :: "n"(NN));
}

// ---------------- weight prep ----------------
template<bool REMAP>
__global__ void transpose_bf16_k(const float* __restrict__ src, __nv_bfloat16* __restrict__ dst,
                                 int Ksrc, int Nsrc, int Kpad)
{
    __shared__ float t[32][33];
    int n0 = blockIdx.x * 32, k0 = blockIdx.y * 32;
    int x = threadIdx.x, y = threadIdx.y;
    #pragma unroll
    for (int i = 0; i < 32; i += 8) {
        int k = k0 + y + i, j = n0 + x;
        int c = REMAP ? ((j >> 1) + (j & 1) * HID) : j;
        int nlim = REMAP ? HID2 : Nsrc;
        t[y + i][x] = (k < Ksrc && j < nlim) ? src[(size_t)k * Nsrc + c] : 0.0f;
    }
    __syncthreads();
    #pragma unroll
    for (int i = 0; i < 32; i += 8) {
        int n = n0 + y + i, k = k0 + x;
        dst[(size_t)n * Kpad + k] = __float2bfloat16(t[x][y + i]);
    }
}
__global__ void b1i_kernel(const float* __restrict__ b1)
{
    int j = blockIdx.x * 256 + threadIdx.x;
    if (j < HID2P) g_b1i[j] = (j < HID2) ? b1[(j >> 1) + (j & 1) * HID] : 0.0f;
}

// ---------------- LayerNorm (emits bf16) ----------------
__global__ void ln_kernel(const float* __restrict__ x,
                          const float* __restrict__ gamma,
                          const float* __restrict__ beta,
                          __nv_bfloat16* __restrict__ out)
{
    int row = blockIdx.x;
    int tid = threadIdx.x;
    const float* xr = x + (size_t)row * DMODEL;
    float v0 = xr[tid];
    float v1 = xr[tid + 256];
    float s  = v0 + v1;
    float ss = v0 * v0 + v1 * v1;

    __shared__ float shs[8], shss[8];
    #pragma unroll
    for (int o = 16; o > 0; o >>= 1) {
        s  += __shfl_down_sync(0xffffffffu, s,  o);
        ss += __shfl_down_sync(0xffffffffu, ss, o);
    }
    if ((tid & 31) == 0) { shs[tid >> 5] = s; shss[tid >> 5] = ss; }
    __syncthreads();
    if (tid < 8) {
        s = shs[tid]; ss = shss[tid];
        #pragma unroll
        for (int o = 4; o > 0; o >>= 1) {
            s  += __shfl_down_sync(0xffu, s,  o);
            ss += __shfl_down_sync(0xffu, ss, o);
        }
        if (tid == 0) { shs[0] = s; shss[0] = ss; }
    }
    __syncthreads();
    float mean = shs[0]  * (1.0f / DMODEL);
    float var  = shss[0] * (1.0f / DMODEL) - mean * mean;
    float inv  = rsqrtf(var + 1e-5f);
    __nv_bfloat16* outr = out + (size_t)row * DMODEL;
    outr[tid]       = __float2bfloat16((v0 - mean) * inv * gamma[tid]       + beta[tid]);
    outr[tid + 256] = __float2bfloat16((v1 - mean) * inv * gamma[tid + 256] + beta[tid + 256]);
}

// ---------------- bf16 mma GEMM, 128x128 tile, 3-stage, ldmatrix fragments ----------------
// MODE: 0 f32 out; 1 +res; 2 +bias geglu->bf16 half-width; 3 +bias+res; 4 bf16 out
#define GROWB 80                   // bytes per smem row (40 bf16)
#define GSTGB (128 * GROWB)        // bytes per stage (A or B)
#define GEMM_SMEM (6 * GSTGB)

template<int MODE>
__global__ void __launch_bounds__(256, 2)
gemm_bf16(const __nv_bfloat16* __restrict__ A, const __nv_bfloat16* __restrict__ BT,
          const float* __restrict__ bias, const float* __restrict__ res,
          float* __restrict__ C, int K, int lda, int ldb, int ldc)
{
    extern __shared__ __nv_bfloat16 smem[];
    __nv_bfloat16 (*As)[40] = (__nv_bfloat16(*)[40])smem;
    __nv_bfloat16 (*Bs)[40] = (__nv_bfloat16(*)[40])(smem + 3 * 128 * 40);

    int tid  = threadIdx.x;
    int lane = tid & 31;
    int wid  = tid >> 5;
    int g  = lane >> 2;
    int tg = lane & 3;
    int wm = (wid & 1) * 64;
    int wn = (wid >> 1) * 32;
    int m0 = blockIdx.y * 128, n0 = blockIdx.x * 128;

    // ldmatrix per-thread base addresses (bytes)
    uint32_t smb   = (uint32_t)__cvta_generic_to_shared(smem);
    uint32_t aAddr = smb + (uint32_t)(wm + ((lane >> 3) & 1) * 8 + (lane & 7)) * GROWB
                         + (uint32_t)(lane >> 4) * 16;
    uint32_t bAddr = smb + 3 * GSTGB
                         + (uint32_t)(wn + ((lane >> 4) & 1) * 8 + (lane & 7)) * GROWB
                         + (uint32_t)((lane >> 3) & 1) * 16;

    float c[4][4][4];
    #pragma unroll
    for (int i = 0; i < 4; i++)
        #pragma unroll
        for (int j = 0; j < 4; j++)
            #pragma unroll
            for (int l = 0; l < 4; l++) c[i][j][l] = 0.0f;

    int T = K >> 5;

    auto stage = [&](int st, int k0) {
        #pragma unroll
        for (int i = 0; i < 2; i++) {
            int idx = i * 256 + tid;
            int row = idx >> 2, c8 = (idx & 3) * 8;
            cp16(&As[st * 128 + row][c8], A + (size_t)(m0 + row) * lda + k0 + c8);
            cp16(&Bs[st * 128 + row][c8], BT + (size_t)(n0 + row) * ldb + k0 + c8);
        }
        cp_commit();
    };

    stage(0, 0);
    if (T > 1) stage(1, 32);

    for (int kt = 0; kt < T; kt++) {
        if (kt + 1 < T) { cp_wait<1>(); } else { cp_wait<0>(); }
        __syncthreads();
        if (kt + 2 < T) stage((kt + 2) % 3, (kt + 2) * 32);

        uint32_t stOff = (uint32_t)(kt % 3) * GSTGB;
        #pragma unroll
        for (int ks = 0; ks < 2; ks++) {
            uint32_t kb = ks * 32;
            unsigned a[4][4], bq[2][4];
            #pragma unroll
            for (int mf = 0; mf < 4; mf++)
                ldsm_x4(a[mf], aAddr + stOff + mf * (16 * GROWB) + kb);
            #pragma unroll
            for (int nfp = 0; nfp < 2; nfp++)
                ldsm_x4(bq[nfp], bAddr + stOff + nfp * (16 * GROWB) + kb);
            #pragma unroll
            for (int mf = 0; mf < 4; mf++)
                #pragma unroll
                for (int nf = 0; nf < 4; nf++)
                    mma_bf16(c[mf][nf], a[mf], &bq[nf >> 1][(nf & 1) * 2]);
        }
    }

    #pragma unroll
    for (int mf = 0; mf < 4; mf++) {
        int r0 = m0 + wm + mf * 16 + g;
        #pragma unroll
        for (int nf = 0; nf < 4; nf++) {
            int col = n0 + wn + nf * 8 + 2 * tg;
            #pragma unroll
            for (int half = 0; half < 2; half++) {
                int r = r0 + half * 8;
                float cx = c[mf][nf][half * 2];
                float cy = c[mf][nf][half * 2 + 1];
                if (MODE == 0) {
                    *(float2*)&C[(size_t)r * ldc + col] = make_float2(cx, cy);
                } else if (MODE == 1) {
                    float2 rr = *(const float2*)&res[(size_t)r * ldc + col];
                    *(float2*)&C[(size_t)r * ldc + col] =
                        make_float2(cx + rr.x, cy + rr.y);
                } else if (MODE == 2) {
                    float xa = cx + bias[col];
                    float yg = cy + bias[col + 1];
                    float ge = 0.5f * yg * (1.0f + erff(yg * 0.70710678118654752f));
                    ((__nv_bfloat16*)C)[(size_t)r * ldc + (col >> 1)] =
                        __float2bfloat16(xa * ge);
                } else if (MODE == 3) {
                    float2 rr = *(const float2*)&res[(size_t)r * ldc + col];
                    *(float2*)&C[(size_t)r * ldc + col] =
                        make_float2(cx + bias[col] + rr.x,
                                    cy + bias[col + 1] + rr.y);
                } else {
                    __nv_bfloat162 o2;
                    o2.x = __float2bfloat16(cx);
                    o2.y = __float2bfloat16(cy);
                    *(__nv_bfloat162*)&((__nv_bfloat16*)C)[(size_t)r * ldc + col] = o2;
                }
            }
        }
    }
}

// ---------------- QKV split + l2norm + scale + rotary xpos ----------------
__global__ void qkv_rotary_kernel(const float* __restrict__ q_scale,
                                  const float* __restrict__ k_scale)
{
    int lane = threadIdx.x & 31;
    int warp = threadIdx.x >> 5;
    long task = (long)blockIdx.x * 4 + warp;
    int b = (int)(task / ((long)SEQ * NH));
    long rem = task - (long)b * SEQ * NH;
    int n = (int)(rem / NH);
    int h = (int)(rem - (long)n * NH);

    size_t base = ((size_t)b * SEQ + n) * QKVN + (size_t)h * DH;
    float q0 = __bfloat162float(g_qkvb[base + lane]);
    float q1 = __bfloat162float(g_qkvb[base + 32 + lane]);
    float k0 = __bfloat162float(g_qkvb[base + 512 + lane]);
    float k1 = __bfloat162float(g_qkvb[base + 512 + 32 + lane]);
    float v0 = __bfloat162float(g_qkvb[base + 1024 + lane]);
    float v1 = __bfloat162float(g_qkvb[base + 1024 + 32 + lane]);

    float sq = q0 * q0 + q1 * q1;
    float sk = k0 * k0 + k1 * k1;
    #pragma unroll
    for (int o = 16; o > 0; o >>= 1) {
        sq += __shfl_xor_sync(0xffffffffu, sq, o);
        sk += __shfl_xor_sync(0xffffffffu, sk, o);
    }
    float qinv = 1.0f / fmaxf(sqrtf(sq), 1e-12f);
    float kinv = 1.0f / fmaxf(sqrtf(sk), 1e-12f);
    q0 = q0 * qinv * q_scale[lane];
    q1 = q1 * qinv * q_scale[lane + 32];
    k0 = k0 * kinv * k_scale[lane];
    k1 = k1 * kinv * k_scale[lane + 32];

    float t    = (float)n;
    float invf = exp2f((float)lane * (-13.287712379549449f / 32.0f));
    float fr   = t * invf;
    float cs = cosf(fr), sn = sinf(fr);
    float sv = (2.0f * (float)lane + 0.4f * 64.0f) / (1.4f * 64.0f);
    float pw = (t - (float)(SEQ / 2)) / (float)(WSIZE / 2);
    float xs = exp2f(pw * log2f(sv));
    float ixs = 1.0f / xs;

    const float QSC = 11.541560327111708f;   // 8 * log2(e)
    float qo0 = (q0 * cs - q1 * sn) * xs;
    float qo1 = (q1 * cs + q0 * sn) * xs;
    float ko0 = (k0 * cs - k1 * sn) * ixs;
    float ko1 = (k1 * cs + k0 * sn) * ixs;

    size_t obase = ((size_t)(b * NH + h) * SEQ + n) * DH;
    g_q[obase + lane]      = __float2bfloat16(QSC * qo0);
    g_q[obase + 32 + lane] = __float2bfloat16(QSC * qo1);
    g_k[obase + lane]      = __float2bfloat16(ko0);
    g_k[obase + 32 + lane] = __float2bfloat16(ko1);
    g_v[obase + lane]      = __float2bfloat16(v0);
    g_v[obase + 32 + lane] = __float2bfloat16(v1);
}

// ---------------- local windowed attention: QK + PV both bf16 mma ----------------
// K, V bf16 in smem, natural [key][dim] layout (stride 72 bf16 = 144 B).
// V fragments via ldmatrix.x4.trans; P packed to bf16x2 in registers.
__global__ void __launch_bounds__(256) attn_kernel()
{
    __shared__ __nv_bfloat16 Ks[2][64][72];
    __shared__ __nv_bfloat16 Vs[2][64][72];

    const int tid  = threadIdx.x;
    const int lane = tid & 31;
    const int wq   = tid >> 5;
    const int g    = lane >> 2;
    const int tg   = lane & 3;
    const int qb   = blockIdx.x;
    const int bh   = blockIdx.y;
    const int t0   = qb * 128;
    const int w    = t0 >> 9;
    const int rstart = (w > 0) ? 0 : ((512 - (t0 & 511)) >> 6);

    // V ldmatrix per-thread base address
    uint32_t vsb   = (uint32_t)__cvta_generic_to_shared(&Vs[0][0][0]);
    uint32_t vAddr = vsb + (uint32_t)(((lane >> 3) & 1) * 8 + (lane & 7)) * 144
                         + (uint32_t)(lane >> 4) * 16;

    // Q fragments (bf16, pre-scaled): 4 k-steps of 16
    unsigned qf[4][4];
    {
        const __nv_bfloat16* qb0 = g_q + ((size_t)bh * SEQ + t0 + wq * 16) * DH;
        #pragma unroll
        for (int kc = 0; kc < 4; kc++) {
            qf[kc][0] = *(const unsigned*)&qb0[(size_t)g * DH + kc * 16 + 2 * tg];
            qf[kc][1] = *(const unsigned*)&qb0[(size_t)(g + 8) * DH + kc * 16 + 2 * tg];
            qf[kc][2] = *(const unsigned*)&qb0[(size_t)g * DH + kc * 16 + 2 * tg + 8];
            qf[kc][3] = *(const unsigned*)&qb0[(size_t)(g + 8) * DH + kc * 16 + 2 * tg + 8];
        }
    }

    float o[8][4];
    #pragma unroll
    for (int i = 0; i < 8; i++)
        #pragma unroll
        for (int j = 0; j < 4; j++) o[i][j] = 0.0f;
    float d0 = 0.0f, d1 = 0.0f;

    const __nv_bfloat16* kbase = g_k + (size_t)bh * SEQ * DH;
    const __nv_bfloat16* vbase = g_v + (size_t)bh * SEQ * DH;

    auto stage = [&](int buf, int kg0) {
        #pragma unroll
        for (int i = 0; i < 2; i++) {
            int idx = i * 256 + tid;
            int kk = idx >> 3, d8 = (idx & 7) * 8;
            cp16(&Ks[buf][kk][d8], kbase + (size_t)(kg0 + kk) * DH + d8);
            cp16(&Vs[buf][kk][d8], vbase + (size_t)(kg0 + kk) * DH + d8);
        }
        cp_commit();
    };

    stage(0, t0 - 512 + 64 * rstart);

    const int q0r = wq * 16 + g;

    for (int r = rstart; r <= 9; r++) {
        int buf = (r - rstart) & 1;
        if (r < 9) {
            stage(buf ^ 1, t0 - 512 + 64 * (r + 1));
            cp_wait<1>();
        } else {
            cp_wait<0>();
        }
        __syncthreads();

        // S = Qscaled @ K^T (bf16)
        float s[8][4];
        #pragma unroll
        for (int i = 0; i < 8; i++)
            #pragma unroll
            for (int j = 0; j < 4; j++) s[i][j] = 0.0f;

        #pragma unroll
        for (int kc = 0; kc < 4; kc++) {
            #pragma unroll
            for (int nf = 0; nf < 8; nf++) {
                unsigned b[2];
                const __nv_bfloat16* kr = &Ks[buf][nf * 8 + g][kc * 16 + 2 * tg];
                b[0] = *(const unsigned*)kr;
                b[1] = *(const unsigned*)(kr + 8);
                mma_bf16(s[nf], qf[kc], b);
            }
        }

        // mask + exp2
        float p[8][4];
        #pragma unroll
        for (int nf = 0; nf < 8; nf++) {
            int j0  = nf * 8 + 2 * tg;
            int jr0 = 64 * r - 512 + j0;
            int jr1 = jr0 + 1;
            bool ok0 = (jr0 <= q0r)     && (jr0 >= q0r - 512);
            bool ok1 = (jr1 <= q0r)     && (jr1 >= q0r - 512);
            bool ok2 = (jr0 <= q0r + 8) && (jr0 >= q0r - 504);
            bool ok3 = (jr1 <= q0r + 8) && (jr1 >= q0r - 504);
            p[nf][0] = ok0 ? ex2f(s[nf][0]) : 0.0f;
            p[nf][1] = ok1 ? ex2f(s[nf][1]) : 0.0f;
            p[nf][2] = ok2 ? ex2f(s[nf][2]) : 0.0f;
            p[nf][3] = ok3 ? ex2f(s[nf][3]) : 0.0f;
            d0 += p[nf][0] + p[nf][1];
            d1 += p[nf][2] + p[nf][3];
        }

        // O += P @ V (bf16 mma; V fragments via ldmatrix.trans)
        uint32_t vbufAddr = vAddr + (uint32_t)buf * (64 * 144);
        #pragma unroll
        for (int kc = 0; kc < 4; kc++) {
            unsigned a[4];
            a[0] = packbf2(p[2 * kc][0],     p[2 * kc][1]);
            a[1] = packbf2(p[2 * kc][2],     p[2 * kc][3]);
            a[2] = packbf2(p[2 * kc + 1][0], p[2 * kc + 1][1]);
            a[3] = packbf2(p[2 * kc + 1][2], p[2 * kc + 1][3]);
            #pragma unroll
            for (int nfp = 0; nfp < 4; nfp++) {
                unsigned bv[4];
                ldsm_x4_t(bv, vbufAddr + (uint32_t)kc * (16 * 144) + (uint32_t)nfp * 32);
                mma_bf16(o[2 * nfp],     a, &bv[0]);
                mma_bf16(o[2 * nfp + 1], a, &bv[2]);
            }
        }
        __syncthreads();
    }

    d0 += __shfl_xor_sync(0xffffffffu, d0, 1);
    d0 += __shfl_xor_sync(0xffffffffu, d0, 2);
    d1 += __shfl_xor_sync(0xffffffffu, d1, 1);
    d1 += __shfl_xor_sync(0xffffffffu, d1, 2);
    float i0 = 1.0f / d0, i1 = 1.0f / d1;

    int b = bh >> 3, h = bh & 7;
    int row0 = t0 + wq * 16 + g;
    __nv_bfloat16* ob = g_o + (size_t)b * SEQ * DMODEL + h * DH;
    #pragma unroll
    for (int nf = 0; nf < 8; nf++) {
        int col = nf * 8 + 2 * tg;
        __nv_bfloat162 lo, hi;
        lo.x = __float2bfloat16(o[nf][0] * i0);
        lo.y = __float2bfloat16(o[nf][1] * i0);
        hi.x = __float2bfloat16(o[nf][2] * i1);
        hi.y = __float2bfloat16(o[nf][3] * i1);
        *(__nv_bfloat162*)&ob[(size_t)row0 * DMODEL + col]       = lo;
        *(__nv_bfloat162*)&ob[(size_t)(row0 + 8) * DMODEL + col] = hi;
    }
}

// ---------------- launch ----------------
extern "C" void kernel_launch(void* const* d_in, const int* in_sizes, int n_in,
                              void* d_out, int out_size)
{
    const float* x     = (const float*)d_in[0];
    const float* ln1g  = (const float*)d_in[1];
    const float* ln1b  = (const float*)d_in[2];
    const float* Wqkv  = (const float*)d_in[3];
    const float* qsc   = (const float*)d_in[4];
    const float* ksc   = (const float*)d_in[5];
    const float* Wout  = (const float*)d_in[6];
    const float* ln2g  = (const float*)d_in[7];
    const float* ln2b  = (const float*)d_in[8];
    const float* W1    = (const float*)d_in[9];
    const float* b1    = (const float*)d_in[10];
    const float* W2    = (const float*)d_in[11];
    const float* b2    = (const float*)d_in[12];
    float* out = (float*)d_out;

    __nv_bfloat16 *ph, *pqkvb, *po, *pg, *pWqkvT, *pWoutT, *pW1iT, *pW2T;
    float *px1, *pb1i;
    cudaGetSymbolAddress((void**)&ph,     g_h);
    cudaGetSymbolAddress((void**)&pqkvb,  g_qkvb);
    cudaGetSymbolAddress((void**)&po,     g_o);
    cudaGetSymbolAddress((void**)&px1,    g_x1);
    cudaGetSymbolAddress((void**)&pg,     g_gate);
    cudaGetSymbolAddress((void**)&pWqkvT, g_WqkvT);
    cudaGetSymbolAddress((void**)&pWoutT, g_WoutT);
    cudaGetSymbolAddress((void**)&pW1iT,  g_W1iT);
    cudaGetSymbolAddress((void**)&pW2T,   g_W2T);
    cudaGetSymbolAddress((void**)&pb1i,   g_b1i);

    cudaFuncSetAttribute(gemm_bf16<0>, cudaFuncAttributeMaxDynamicSharedMemorySize, GEMM_SMEM);
    cudaFuncSetAttribute(gemm_bf16<1>, cudaFuncAttributeMaxDynamicSharedMemorySize, GEMM_SMEM);
    cudaFuncSetAttribute(gemm_bf16<2>, cudaFuncAttributeMaxDynamicSharedMemorySize, GEMM_SMEM);
    cudaFuncSetAttribute(gemm_bf16<3>, cudaFuncAttributeMaxDynamicSharedMemorySize, GEMM_SMEM);
    cudaFuncSetAttribute(gemm_bf16<4>, cudaFuncAttributeMaxDynamicSharedMemorySize, GEMM_SMEM);

    // 0) weight prep
    {
        dim3 blk(32, 8);
        transpose_bf16_k<false><<<dim3(QKVN / 32, DMODEL / 32), blk>>>(
            Wqkv, pWqkvT, DMODEL, QKVN, DMODEL);
        transpose_bf16_k<false><<<dim3(DMODEL / 32, DMODEL / 32), blk>>>(
            Wout, pWoutT, DMODEL, DMODEL, DMODEL);
        transpose_bf16_k<true><<<dim3(HID2P / 32, DMODEL / 32), blk>>>(
            W1, pW1iT, DMODEL, HID2, DMODEL);
        transpose_bf16_k<false><<<dim3(DMODEL / 32, KFF2 / 32), blk>>>(
            W2, pW2T, HID, DMODEL, KFF2);
        b1i_kernel<<<(HID2P + 255) / 256, 256>>>(b1);
    }

    // 1) LN1 -> h (bf16)
    ln_kernel<<<BNROWS, 256>>>(x, ln1g, ln1b, ph);
    // 2) QKV GEMM -> qkv (bf16)
    gemm_bf16<4><<<dim3(QKVN / 128, BNROWS / 128), 256, GEMM_SMEM>>>(
        ph, pWqkvT, nullptr, nullptr, (float*)pqkvb, DMODEL, DMODEL, DMODEL, QKVN);
    // 3) split + l2norm + rotary xpos -> q,k,v bf16
    qkv_rotary_kernel<<<(BATCH * SEQ * NH) / 4, 128>>>(qsc, ksc);
    // 4) local attention -> o (bf16)
    attn_kernel<<<dim3(SEQ / 128, BHEADS), 256>>>();
    // 5) out projection + residual -> x1 (fp32)
    gemm_bf16<1><<<dim3(DMODEL / 128, BNROWS / 128), 256, GEMM_SMEM>>>(
        po, pWoutT, nullptr, x, px1, DMODEL, DMODEL, DMODEL, DMODEL);
    // 6) LN2 -> h (bf16)
    ln_kernel<<<BNROWS, 256>>>(px1, ln2g, ln2b, ph);
    // 7) FF1 + fused geglu -> gate (bf16)
    gemm_bf16<2><<<dim3(HID2P / 128, BNROWS / 128), 256, GEMM_SMEM>>>(
        ph, pW1iT, pb1i, nullptr, (float*)pg, DMODEL, DMODEL, DMODEL, KFF2);
    // 8) FF2 + b2 + residual -> out
    gemm_bf16<3><<<dim3(DMODEL / 128, BNROWS / 128), 256, GEMM_SMEM>>>(
        pg, pW2T, b2, px1, out, KFF2, KFF2, KFF2, DMODEL);
}

// round 11
// speedup vs baseline: 1.9225x; 1.1115x over previous
#include <cuda_runtime.h>
#include <cuda_bf16.h>
#include <math.h>
#include <stdint.h>

// ---------------- problem constants ----------------
#define BATCH   2
#define SEQ     8192
#define DMODEL  512
#define NH      8
#define DH      64
#define BHEADS  16
#define BNROWS  16384
#define QKVN    1536
#define HID     1365
#define HID2    2730
#define HID2P   2816
#define KFF2    1408
#define WSIZE   512

// ---------------- scratch buffers ----------------
__device__ __nv_bfloat16 g_h   [(size_t)BNROWS * DMODEL];
__device__ __nv_bfloat16 g_qkvb[(size_t)BNROWS * QKVN];
__device__ __nv_bfloat16 g_q   [(size_t)BHEADS * SEQ * DH];   // pre-scaled by 8*log2e
__device__ __nv_bfloat16 g_k   [(size_t)BHEADS * SEQ * DH];
__device__ __nv_bfloat16 g_v   [(size_t)BHEADS * SEQ * DH];
__device__ __nv_bfloat16 g_o   [(size_t)BNROWS * DMODEL];
__device__ float         g_x1  [(size_t)BNROWS * DMODEL];
__device__ __nv_bfloat16 g_gate[(size_t)BNROWS * KFF2];
__device__ __nv_bfloat16 g_WqkvT[(size_t)QKVN * DMODEL];
__device__ __nv_bfloat16 g_WoutT[(size_t)DMODEL * DMODEL];
__device__ __nv_bfloat16 g_W1iT [(size_t)HID2P * DMODEL];
__device__ __nv_bfloat16 g_W2T  [(size_t)DMODEL * KFF2];
__device__ float         g_b1i  [HID2P];

// ---------------- helpers ----------------
__device__ __forceinline__ float ex2f(float x) {
    float y;
    asm("ex2.approx.f32 %0, %1;" : "=f"(y) : "f"(x));
    return y;
}
__device__ __forceinline__ void mma_bf16(float c[4], const unsigned a[4], const unsigned b[2]) {
    asm volatile(
        "mma.sync.aligned.m16n8k16.row.col.f32.bf16.bf16.f32 "
        "{%0,%1,%2,%3}, {%4,%5,%6,%7}, {%8,%9}, {%0,%1,%2,%3};"
        : "+f"(c[0]), "+f"(c[1]), "+f"(c[2]), "+f"(c[3])
        : "r"(a[0]), "r"(a[1]), "r"(a[2]), "r"(a[3]), "r"(b[0]), "r"(b[1]));
}
__device__ __forceinline__ void ldsm_x4(unsigned r[4], uint32_t addr) {
    asm volatile("ldmatrix.sync.aligned.m8n8.x4.shared.b16 {%0,%1,%2,%3}, [%4];"
                 : "=r"(r[0]), "=r"(r[1]), "=r"(r[2]), "=r"(r[3]) : "r"(addr));
}
__device__ __forceinline__ void ldsm_x4_t(unsigned r[4], uint32_t addr) {
    asm volatile("ldmatrix.sync.aligned.m8n8.x4.trans.shared.b16 {%0,%1,%2,%3}, [%4];"
                 : "=r"(r[0]), "=r"(r[1]), "=r"(r[2]), "=r"(r[3]) : "r"(addr));
}
__device__ __forceinline__ unsigned packbf2(float lo, float hi) {
    unsigned d;
    asm("cvt.rn.bf16x2.f32 %0, %1, %2;" : "=r"(d) : "f"(hi), "f"(lo));
    return d;
}
__device__ __forceinline__ void cp16(const void* s, const void* g) {
    unsigned sa = (unsigned)__cvta_generic_to_shared(s);
    asm volatile("cp.async.cg.shared.global [%0], [%1], 16;" :: "r"(sa), "l"(g));
}
__device__ __forceinline__ void cp_commit() { asm volatile("cp.async.commit_group;"); }
template<int NN> __device__ __forceinline__ void cp_wait() {
    asm volatile("cp.async.wait_group %0;" :: "n"(NN));
}

// ---------------- weight prep ----------------
template<bool REMAP>
__global__ void transpose_bf16_k(const float* __restrict__ src, __nv_bfloat16* __restrict__ dst,
                                 int Ksrc, int Nsrc, int Kpad)
{
    __shared__ float t[32][33];
    int n0 = blockIdx.x * 32, k0 = blockIdx.y * 32;
    int x = threadIdx.x, y = threadIdx.y;
    #pragma unroll
    for (int i = 0; i < 32; i += 8) {
        int k = k0 + y + i, j = n0 + x;
        int c = REMAP ? ((j >> 1) + (j & 1) * HID) : j;
        int nlim = REMAP ? HID2 : Nsrc;
        t[y + i][x] = (k < Ksrc && j < nlim) ? src[(size_t)k * Nsrc + c] : 0.0f;
    }
    __syncthreads();
    #pragma unroll
    for (int i = 0; i < 32; i += 8) {
        int n = n0 + y + i, k = k0 + x;
        dst[(size_t)n * Kpad + k] = __float2bfloat16(t[x][y + i]);
    }
}
__global__ void b1i_kernel(const float* __restrict__ b1)
{
    int j = blockIdx.x * 256 + threadIdx.x;
    if (j < HID2P) g_b1i[j] = (j < HID2) ? b1[(j >> 1) + (j & 1) * HID] : 0.0f;
}

// ---------------- LayerNorm (emits bf16) ----------------
__global__ void ln_kernel(const float* __restrict__ x,
                          const float* __restrict__ gamma,
                          const float* __restrict__ beta,
                          __nv_bfloat16* __restrict__ out)
{
    int row = blockIdx.x;
    int tid = threadIdx.x;
    const float* xr = x + (size_t)row * DMODEL;
    float v0 = xr[tid];
    float v1 = xr[tid + 256];
    float s  = v0 + v1;
    float ss = v0 * v0 + v1 * v1;

    __shared__ float shs[8], shss[8];
    #pragma unroll
    for (int o = 16; o > 0; o >>= 1) {
        s  += __shfl_down_sync(0xffffffffu, s,  o);
        ss += __shfl_down_sync(0xffffffffu, ss, o);
    }
    if ((tid & 31) == 0) { shs[tid >> 5] = s; shss[tid >> 5] = ss; }
    __syncthreads();
    if (tid < 8) {
        s = shs[tid]; ss = shss[tid];
        #pragma unroll
        for (int o = 4; o > 0; o >>= 1) {
            s  += __shfl_down_sync(0xffu, s,  o);
            ss += __shfl_down_sync(0xffu, ss, o);
        }
        if (tid == 0) { shs[0] = s; shss[0] = ss; }
    }
    __syncthreads();
    float mean = shs[0]  * (1.0f / DMODEL);
    float var  = shss[0] * (1.0f / DMODEL) - mean * mean;
    float inv  = rsqrtf(var + 1e-5f);
    __nv_bfloat16* outr = out + (size_t)row * DMODEL;
    outr[tid]       = __float2bfloat16((v0 - mean) * inv * gamma[tid]       + beta[tid]);
    outr[tid + 256] = __float2bfloat16((v1 - mean) * inv * gamma[tid + 256] + beta[tid + 256]);
}

// ---------------- bf16 mma GEMM, 128x128 tile, 4-stage, ldmatrix fragments ----------------
// MODE: 0 f32 out; 1 +res; 2 +bias geglu->bf16 half-width (smem-bounced);
//       3 +bias+res; 4 bf16 out (smem-bounced)
#define GROWB 80                   // bytes per smem row (40 bf16)
#define GSTGB (128 * GROWB)        // bytes per stage (A or B)
#define GEMM_SMEM (8 * GSTGB)      // 4 stages x (A + B)

template<int MODE>
__global__ void __launch_bounds__(256, 2)
gemm_bf16(const __nv_bfloat16* __restrict__ A, const __nv_bfloat16* __restrict__ BT,
          const float* __restrict__ bias, const float* __restrict__ res,
          float* __restrict__ C, int K, int lda, int ldb, int ldc)
{
    extern __shared__ __nv_bfloat16 smem[];
    __nv_bfloat16 (*As)[40] = (__nv_bfloat16(*)[40])smem;
    __nv_bfloat16 (*Bs)[40] = (__nv_bfloat16(*)[40])(smem + 4 * 128 * 40);

    int tid  = threadIdx.x;
    int lane = tid & 31;
    int wid  = tid >> 5;
    int g  = lane >> 2;
    int tg = lane & 3;
    int wm = (wid & 1) * 64;
    int wn = (wid >> 1) * 32;
    int m0 = blockIdx.y * 128, n0 = blockIdx.x * 128;

    uint32_t smb   = (uint32_t)__cvta_generic_to_shared(smem);
    uint32_t aAddr = smb + (uint32_t)(wm + ((lane >> 3) & 1) * 8 + (lane & 7)) * GROWB
                         + (uint32_t)(lane >> 4) * 16;
    uint32_t bAddr = smb + 4 * GSTGB
                         + (uint32_t)(wn + ((lane >> 4) & 1) * 8 + (lane & 7)) * GROWB
                         + (uint32_t)((lane >> 3) & 1) * 16;

    float c[4][4][4];
    #pragma unroll
    for (int i = 0; i < 4; i++)
        #pragma unroll
        for (int j = 0; j < 4; j++)
            #pragma unroll
            for (int l = 0; l < 4; l++) c[i][j][l] = 0.0f;

    int T = K >> 5;

    auto stage = [&](int st, int k0) {
        #pragma unroll
        for (int i = 0; i < 2; i++) {
            int idx = i * 256 + tid;
            int row = idx >> 2, c8 = (idx & 3) * 8;
            cp16(&As[st * 128 + row][c8], A + (size_t)(m0 + row) * lda + k0 + c8);
            cp16(&Bs[st * 128 + row][c8], BT + (size_t)(n0 + row) * ldb + k0 + c8);
        }
        cp_commit();
    };

    stage(0, 0);
    if (T > 1) stage(1, 32);
    if (T > 2) stage(2, 64);

    for (int kt = 0; kt < T; kt++) {
        if (kt + 2 < T)      { cp_wait<2>(); }
        else if (kt + 1 < T) { cp_wait<1>(); }
        else                 { cp_wait<0>(); }
        __syncthreads();
        if (kt + 3 < T) stage((kt + 3) & 3, (kt + 3) * 32);

        uint32_t stOff = (uint32_t)(kt & 3) * GSTGB;
        #pragma unroll
        for (int ks = 0; ks < 2; ks++) {
            uint32_t kb = ks * 32;
            unsigned a[4][4], bq[2][4];
            #pragma unroll
            for (int mf = 0; mf < 4; mf++)
                ldsm_x4(a[mf], aAddr + stOff + mf * (16 * GROWB) + kb);
            #pragma unroll
            for (int nfp = 0; nfp < 2; nfp++)
                ldsm_x4(bq[nfp], bAddr + stOff + nfp * (16 * GROWB) + kb);
            #pragma unroll
            for (int mf = 0; mf < 4; mf++)
                #pragma unroll
                for (int nf = 0; nf < 4; nf++)
                    mma_bf16(c[mf][nf], a[mf], &bq[nf >> 1][(nf & 1) * 2]);
        }
    }

    if (MODE == 2 || MODE == 4) {
        // smem-bounced coalesced bf16 stores
        __syncthreads();   // all warps done reading stage smem
        __nv_bfloat16* Cb = (__nv_bfloat16*)C;
        if (MODE == 2) {
            __nv_bfloat16 (*sm2)[72] = (__nv_bfloat16(*)[72])smem;
            #pragma unroll
            for (int mf = 0; mf < 4; mf++) {
                #pragma unroll
                for (int nf = 0; nf < 4; nf++) {
                    int lc = wn / 2 + nf * 4 + tg;
                    #pragma unroll
                    for (int half = 0; half < 2; half++) {
                        int lr = wm + mf * 16 + g + half * 8;
                        int col = n0 + wn + nf * 8 + 2 * tg;
                        float xa = c[mf][nf][half * 2]     + bias[col];
                        float yg = c[mf][nf][half * 2 + 1] + bias[col + 1];
                        float ge = 0.5f * yg * (1.0f + erff(yg * 0.70710678118654752f));
                        sm2[lr][lc] = __float2bfloat16(xa * ge);
                    }
                }
            }
            __syncthreads();
            #pragma unroll
            for (int it = 0; it < 4; it++) {
                int idx = it * 256 + tid;
                int lr = idx >> 3, ch = idx & 7;
                *(float4*)&Cb[(size_t)(m0 + lr) * ldc + (n0 >> 1) + ch * 8] =
                    *(const float4*)&sm2[lr][ch * 8];
            }
        } else {
            __nv_bfloat16 (*sm4)[136] = (__nv_bfloat16(*)[136])smem;
            #pragma unroll
            for (int mf = 0; mf < 4; mf++) {
                #pragma unroll
                for (int nf = 0; nf < 4; nf++) {
                    int lc = wn + nf * 8 + 2 * tg;
                    #pragma unroll
                    for (int half = 0; half < 2; half++) {
                        int lr = wm + mf * 16 + g + half * 8;
                        __nv_bfloat162 o2;
                        o2.x = __float2bfloat16(c[mf][nf][half * 2]);
                        o2.y = __float2bfloat16(c[mf][nf][half * 2 + 1]);
                        *(__nv_bfloat162*)&sm4[lr][lc] = o2;
                    }
                }
            }
            __syncthreads();
            #pragma unroll
            for (int it = 0; it < 8; it++) {
                int idx = it * 256 + tid;
                int lr = idx >> 4, ch = idx & 15;
                *(float4*)&Cb[(size_t)(m0 + lr) * ldc + n0 + ch * 8] =
                    *(const float4*)&sm4[lr][ch * 8];
            }
        }
        return;
    }

    #pragma unroll
    for (int mf = 0; mf < 4; mf++) {
        int r0 = m0 + wm + mf * 16 + g;
        #pragma unroll
        for (int nf = 0; nf < 4; nf++) {
            int col = n0 + wn + nf * 8 + 2 * tg;
            #pragma unroll
            for (int half = 0; half < 2; half++) {
                int r = r0 + half * 8;
                float cx = c[mf][nf][half * 2];
                float cy = c[mf][nf][half * 2 + 1];
                if (MODE == 0) {
                    *(float2*)&C[(size_t)r * ldc + col] = make_float2(cx, cy);
                } else if (MODE == 1) {
                    float2 rr = *(const float2*)&res[(size_t)r * ldc + col];
                    *(float2*)&C[(size_t)r * ldc + col] =
                        make_float2(cx + rr.x, cy + rr.y);
                } else {
                    float2 rr = *(const float2*)&res[(size_t)r * ldc + col];
                    *(float2*)&C[(size_t)r * ldc + col] =
                        make_float2(cx + bias[col] + rr.x,
                                    cy + bias[col + 1] + rr.y);
                }
            }
        }
    }
}

// ---------------- QKV split + l2norm + scale + rotary xpos ----------------
__global__ void qkv_rotary_kernel(const float* __restrict__ q_scale,
                                  const float* __restrict__ k_scale)
{
    int lane = threadIdx.x & 31;
    int warp = threadIdx.x >> 5;
    long task = (long)blockIdx.x * 4 + warp;
    int b = (int)(task / ((long)SEQ * NH));
    long rem = task - (long)b * SEQ * NH;
    int n = (int)(rem / NH);
    int h = (int)(rem - (long)n * NH);

    size_t base = ((size_t)b * SEQ + n) * QKVN + (size_t)h * DH;
    float q0 = __bfloat162float(g_qkvb[base + lane]);
    float q1 = __bfloat162float(g_qkvb[base + 32 + lane]);
    float k0 = __bfloat162float(g_qkvb[base + 512 + lane]);
    float k1 = __bfloat162float(g_qkvb[base + 512 + 32 + lane]);
    float v0 = __bfloat162float(g_qkvb[base + 1024 + lane]);
    float v1 = __bfloat162float(g_qkvb[base + 1024 + 32 + lane]);

    float sq = q0 * q0 + q1 * q1;
    float sk = k0 * k0 + k1 * k1;
    #pragma unroll
    for (int o = 16; o > 0; o >>= 1) {
        sq += __shfl_xor_sync(0xffffffffu, sq, o);
        sk += __shfl_xor_sync(0xffffffffu, sk, o);
    }
    float qinv = 1.0f / fmaxf(sqrtf(sq), 1e-12f);
    float kinv = 1.0f / fmaxf(sqrtf(sk), 1e-12f);
    q0 = q0 * qinv * q_scale[lane];
    q1 = q1 * qinv * q_scale[lane + 32];
    k0 = k0 * kinv * k_scale[lane];
    k1 = k1 * kinv * k_scale[lane + 32];

    float t    = (float)n;
    float invf = exp2f((float)lane * (-13.287712379549449f / 32.0f));
    float fr   = t * invf;
    float cs = cosf(fr), sn = sinf(fr);
    float sv = (2.0f * (float)lane + 0.4f * 64.0f) / (1.4f * 64.0f);
    float pw = (t - (float)(SEQ / 2)) / (float)(WSIZE / 2);
    float xs = exp2f(pw * log2f(sv));
    float ixs = 1.0f / xs;

    const float QSC = 11.541560327111708f;   // 8 * log2(e)
    float qo0 = (q0 * cs - q1 * sn) * xs;
    float qo1 = (q1 * cs + q0 * sn) * xs;
    float ko0 = (k0 * cs - k1 * sn) * ixs;
    float ko1 = (k1 * cs + k0 * sn) * ixs;

    size_t obase = ((size_t)(b * NH + h) * SEQ + n) * DH;
    g_q[obase + lane]      = __float2bfloat16(QSC * qo0);
    g_q[obase + 32 + lane] = __float2bfloat16(QSC * qo1);
    g_k[obase + lane]      = __float2bfloat16(ko0);
    g_k[obase + 32 + lane] = __float2bfloat16(ko1);
    g_v[obase + lane]      = __float2bfloat16(v0);
    g_v[obase + 32 + lane] = __float2bfloat16(v1);
}

// ---------------- local windowed attention: QK + PV bf16 mma, 3-buffer ----------------
#define AKROW 144                       // bytes per K/V smem row (72 bf16)
#define ABUF  (64 * AKROW)              // bytes per buffer per matrix
#define ATTN_SMEM (6 * ABUF)            // 3 buffers x (K + V)

__global__ void __launch_bounds__(256) attn_kernel()
{
    extern __shared__ char asmem[];
    __nv_bfloat16 (*Ks)[72] = (__nv_bfloat16(*)[72])asmem;
    __nv_bfloat16 (*Vs)[72] = (__nv_bfloat16(*)[72])(asmem + 3 * ABUF);

    const int tid  = threadIdx.x;
    const int lane = tid & 31;
    const int wq   = tid >> 5;
    const int g    = lane >> 2;
    const int tg   = lane & 3;
    const int qb   = blockIdx.x;
    const int bh   = blockIdx.y;
    const int t0   = qb * 128;
    const int w    = t0 >> 9;
    const int rstart = (w > 0) ? 0 : ((512 - (t0 & 511)) >> 6);

    uint32_t vsb   = (uint32_t)__cvta_generic_to_shared(&Vs[0][0]);
    uint32_t vAddr = vsb + (uint32_t)(((lane >> 3) & 1) * 8 + (lane & 7)) * AKROW
                         + (uint32_t)(lane >> 4) * 16;

    unsigned qf[4][4];
    {
        const __nv_bfloat16* qb0 = g_q + ((size_t)bh * SEQ + t0 + wq * 16) * DH;
        #pragma unroll
        for (int kc = 0; kc < 4; kc++) {
            qf[kc][0] = *(const unsigned*)&qb0[(size_t)g * DH + kc * 16 + 2 * tg];
            qf[kc][1] = *(const unsigned*)&qb0[(size_t)(g + 8) * DH + kc * 16 + 2 * tg];
            qf[kc][2] = *(const unsigned*)&qb0[(size_t)g * DH + kc * 16 + 2 * tg + 8];
            qf[kc][3] = *(const unsigned*)&qb0[(size_t)(g + 8) * DH + kc * 16 + 2 * tg + 8];
        }
    }

    float o[8][4];
    #pragma unroll
    for (int i = 0; i < 8; i++)
        #pragma unroll
        for (int j = 0; j < 4; j++) o[i][j] = 0.0f;
    float d0 = 0.0f, d1 = 0.0f;

    const __nv_bfloat16* kbase = g_k + (size_t)bh * SEQ * DH;
    const __nv_bfloat16* vbase = g_v + (size_t)bh * SEQ * DH;

    auto stage = [&](int buf, int r) {
        int kg0 = t0 - 512 + 64 * r;
        #pragma unroll
        for (int i = 0; i < 2; i++) {
            int idx = i * 256 + tid;
            int kk = idx >> 3, d8 = (idx & 7) * 8;
            cp16(&Ks[buf * 64 + kk][d8], kbase + (size_t)(kg0 + kk) * DH + d8);
            cp16(&Vs[buf * 64 + kk][d8], vbase + (size_t)(kg0 + kk) * DH + d8);
        }
        cp_commit();
    };

    stage(0, rstart);
    if (rstart + 1 <= 9) stage(1, rstart + 1);

    const int q0r = wq * 16 + g;

    for (int r = rstart; r <= 9; r++) {
        int i  = r - rstart;
        int bi = i % 3;
        if (r < 9) { cp_wait<1>(); } else { cp_wait<0>(); }
        __syncthreads();
        if (r + 2 <= 9) stage((i + 2) % 3, r + 2);

        // S = Qscaled @ K^T (bf16)
        float s[8][4];
        #pragma unroll
        for (int ii = 0; ii < 8; ii++)
            #pragma unroll
            for (int j = 0; j < 4; j++) s[ii][j] = 0.0f;

        #pragma unroll
        for (int kc = 0; kc < 4; kc++) {
            #pragma unroll
            for (int nf = 0; nf < 8; nf++) {
                unsigned b[2];
                const __nv_bfloat16* kr = &Ks[bi * 64 + nf * 8 + g][kc * 16 + 2 * tg];
                b[0] = *(const unsigned*)kr;
                b[1] = *(const unsigned*)(kr + 8);
                mma_bf16(s[nf], qf[kc], b);
            }
        }

        // mask + exp2
        float p[8][4];
        #pragma unroll
        for (int nf = 0; nf < 8; nf++) {
            int j0  = nf * 8 + 2 * tg;
            int jr0 = 64 * r - 512 + j0;
            int jr1 = jr0 + 1;
            bool ok0 = (jr0 <= q0r)     && (jr0 >= q0r - 512);
            bool ok1 = (jr1 <= q0r)     && (jr1 >= q0r - 512);
            bool ok2 = (jr0 <= q0r + 8) && (jr0 >= q0r - 504);
            bool ok3 = (jr1 <= q0r + 8) && (jr1 >= q0r - 504);
            p[nf][0] = ok0 ? ex2f(s[nf][0]) : 0.0f;
            p[nf][1] = ok1 ? ex2f(s[nf][1]) : 0.0f;
            p[nf][2] = ok2 ? ex2f(s[nf][2]) : 0.0f;
            p[nf][3] = ok3 ? ex2f(s[nf][3]) : 0.0f;
            d0 += p[nf][0] + p[nf][1];
            d1 += p[nf][2] + p[nf][3];
        }

        // O += P @ V (bf16; V fragments via ldmatrix.trans)
        uint32_t vbufAddr = vAddr + (uint32_t)bi * ABUF;
        #pragma unroll
        for (int kc = 0; kc < 4; kc++) {
            unsigned a[4];
            a[0] = packbf2(p[2 * kc][0],     p[2 * kc][1]);
            a[1] = packbf2(p[2 * kc][2],     p[2 * kc][3]);
            a[2] = packbf2(p[2 * kc + 1][0], p[2 * kc + 1][1]);
            a[3] = packbf2(p[2 * kc + 1][2], p[2 * kc + 1][3]);
            #pragma unroll
            for (int nfp = 0; nfp < 4; nfp++) {
                unsigned bv[4];
                ldsm_x4_t(bv, vbufAddr + (uint32_t)kc * (16 * AKROW) + (uint32_t)nfp * 32);
                mma_bf16(o[2 * nfp],     a, &bv[0]);
                mma_bf16(o[2 * nfp + 1], a, &bv[2]);
            }
        }
    }

    d0 += __shfl_xor_sync(0xffffffffu, d0, 1);
    d0 += __shfl_xor_sync(0xffffffffu, d0, 2);
    d1 += __shfl_xor_sync(0xffffffffu, d1, 1);
    d1 += __shfl_xor_sync(0xffffffffu, d1, 2);
    float i0 = 1.0f / d0, i1 = 1.0f / d1;

    int b = bh >> 3, h = bh & 7;
    int row0 = t0 + wq * 16 + g;
    __nv_bfloat16* ob = g_o + (size_t)b * SEQ * DMODEL + h * DH;
    #pragma unroll
    for (int nf = 0; nf < 8; nf++) {
        int col = nf * 8 + 2 * tg;
        __nv_bfloat162 lo, hi;
        lo.x = __float2bfloat16(o[nf][0] * i0);
        lo.y = __float2bfloat16(o[nf][1] * i0);
        hi.x = __float2bfloat16(o[nf][2] * i1);
        hi.y = __float2bfloat16(o[nf][3] * i1);
        *(__nv_bfloat162*)&ob[(size_t)row0 * DMODEL + col]       = lo;
        *(__nv_bfloat162*)&ob[(size_t)(row0 + 8) * DMODEL + col] = hi;
    }
}

// ---------------- launch ----------------
extern "C" void kernel_launch(void* const* d_in, const int* in_sizes, int n_in,
                              void* d_out, int out_size)
{
    const float* x     = (const float*)d_in[0];
    const float* ln1g  = (const float*)d_in[1];
    const float* ln1b  = (const float*)d_in[2];
    const float* Wqkv  = (const float*)d_in[3];
    const float* qsc   = (const float*)d_in[4];
    const float* ksc   = (const float*)d_in[5];
    const float* Wout  = (const float*)d_in[6];
    const float* ln2g  = (const float*)d_in[7];
    const float* ln2b  = (const float*)d_in[8];
    const float* W1    = (const float*)d_in[9];
    const float* b1    = (const float*)d_in[10];
    const float* W2    = (const float*)d_in[11];
    const float* b2    = (const float*)d_in[12];
    float* out = (float*)d_out;

    __nv_bfloat16 *ph, *pqkvb, *po, *pg, *pWqkvT, *pWoutT, *pW1iT, *pW2T;
    float *px1, *pb1i;
    cudaGetSymbolAddress((void**)&ph,     g_h);
    cudaGetSymbolAddress((void**)&pqkvb,  g_qkvb);
    cudaGetSymbolAddress((void**)&po,     g_o);
    cudaGetSymbolAddress((void**)&px1,    g_x1);
    cudaGetSymbolAddress((void**)&pg,     g_gate);
    cudaGetSymbolAddress((void**)&pWqkvT, g_WqkvT);
    cudaGetSymbolAddress((void**)&pWoutT, g_WoutT);
    cudaGetSymbolAddress((void**)&pW1iT,  g_W1iT);
    cudaGetSymbolAddress((void**)&pW2T,   g_W2T);
    cudaGetSymbolAddress((void**)&pb1i,   g_b1i);

    cudaFuncSetAttribute(gemm_bf16<0>, cudaFuncAttributeMaxDynamicSharedMemorySize, GEMM_SMEM);
    cudaFuncSetAttribute(gemm_bf16<1>, cudaFuncAttributeMaxDynamicSharedMemorySize, GEMM_SMEM);
    cudaFuncSetAttribute(gemm_bf16<2>, cudaFuncAttributeMaxDynamicSharedMemorySize, GEMM_SMEM);
    cudaFuncSetAttribute(gemm_bf16<3>, cudaFuncAttributeMaxDynamicSharedMemorySize, GEMM_SMEM);
    cudaFuncSetAttribute(gemm_bf16<4>, cudaFuncAttributeMaxDynamicSharedMemorySize, GEMM_SMEM);
    cudaFuncSetAttribute(attn_kernel,  cudaFuncAttributeMaxDynamicSharedMemorySize, ATTN_SMEM);

    // 0) weight prep
    {
        dim3 blk(32, 8);
        transpose_bf16_k<false><<<dim3(QKVN / 32, DMODEL / 32), blk>>>(
            Wqkv, pWqkvT, DMODEL, QKVN, DMODEL);
        transpose_bf16_k<false><<<dim3(DMODEL / 32, DMODEL / 32), blk>>>(
            Wout, pWoutT, DMODEL, DMODEL, DMODEL);
        transpose_bf16_k<true><<<dim3(HID2P / 32, DMODEL / 32), blk>>>(
            W1, pW1iT, DMODEL, HID2, DMODEL);
        transpose_bf16_k<false><<<dim3(DMODEL / 32, KFF2 / 32), blk>>>(
            W2, pW2T, HID, DMODEL, KFF2);
        b1i_kernel<<<(HID2P + 255) / 256, 256>>>(b1);
    }

    // 1) LN1 -> h (bf16)
    ln_kernel<<<BNROWS, 256>>>(x, ln1g, ln1b, ph);
    // 2) QKV GEMM -> qkv (bf16, bounced stores)
    gemm_bf16<4><<<dim3(QKVN / 128, BNROWS / 128), 256, GEMM_SMEM>>>(
        ph, pWqkvT, nullptr, nullptr, (float*)pqkvb, DMODEL, DMODEL, DMODEL, QKVN);
    // 3) split + l2norm + rotary xpos -> q,k,v bf16
    qkv_rotary_kernel<<<(BATCH * SEQ * NH) / 4, 128>>>(qsc, ksc);
    // 4) local attention -> o (bf16)
    attn_kernel<<<dim3(SEQ / 128, BHEADS), 256, ATTN_SMEM>>>();
    // 5) out projection + residual -> x1 (fp32)
    gemm_bf16<1><<<dim3(DMODEL / 128, BNROWS / 128), 256, GEMM_SMEM>>>(
        po, pWoutT, nullptr, x, px1, DMODEL, DMODEL, DMODEL, DMODEL);
    // 6) LN2 -> h (bf16)
    ln_kernel<<<BNROWS, 256>>>(px1, ln2g, ln2b, ph);
    // 7) FF1 + fused geglu -> gate (bf16, bounced stores)
    gemm_bf16<2><<<dim3(HID2P / 128, BNROWS / 128), 256, GEMM_SMEM>>>(
        ph, pW1iT, pb1i, nullptr, (float*)pg, DMODEL, DMODEL, DMODEL, KFF2);
    // 8) FF2 + b2 + residual -> out
    gemm_bf16<3><<<dim3(DMODEL / 128, BNROWS / 128), 256, GEMM_SMEM>>>(
        pg, pW2T, b2, px1, out, KFF2, KFF2, KFF2, DMODEL);
}